// round 2
// baseline (speedup 1.0000x reference)
#include <cuda_runtime.h>
#include <cstdint>
#include <cstddef>

// ---------------- problem constants ----------------
#define BATCH   8
#define P       2784
#define PM1     2783
#define FH      11
#define FW      20
#define HW      220        // FH*FW
#define CIN     512
#define AFC     64
#define DIM     704        // AFC*FH
#define DIM2    1408
#define NWOUT   75         // 2 cls + 73 reg
#define M_TOT   (BATCH*P)  // 22272  (divisible by 128: 174*128)

// ---------------- scratch (static device memory; no allocs allowed) ----------
__device__ float         g_f[BATCH*AFC*HW];                  // conv output
__device__ float         g_feat[(size_t)M_TOT*DIM];          // gathered features
__device__ float         g_att[(size_t)M_TOT*PM1];           // scores -> softmax (in place)
__device__ float         g_attfeat[(size_t)M_TOT*DIM];       // attention output
__device__ unsigned char g_inv[P*FH];                        // normalized invalid mask

// ---------------- invalid-dtype detection + normalization --------------------
// 'invalid' is a numpy bool array; its device dtype may be 1-byte bool, int32,
// or float32 depending on serialization. Inspect only the first P*FH bytes
// (in-bounds under every interpretation), decide deterministically, normalize.
__global__ void k_detect_inv(const unsigned char* __restrict__ raw) {
    __shared__ int f_gt1, f_mod;
    if (threadIdx.x == 0) { f_gt1 = 0; f_mod = 0; }
    __syncthreads();
    const int NB = P * FH;
    int lg = 0, lm = 0;
    for (int i = threadIdx.x; i < NB; i += blockDim.x) {
        unsigned char v = raw[i];
        if (v > 1) lg = 1;                    // only possible for float32 payload
        if (v != 0 && (i & 3) != 0) lm = 1;   // nonzero off 4-byte boundary -> bool
    }
    if (lg) atomicOr(&f_gt1, 1);
    if (lm) atomicOr(&f_mod, 1);
    __syncthreads();
    int mode = f_gt1 ? 2 : (f_mod ? 0 : 1);   // 2=float32, 0=bool, 1=int32
    for (int i = threadIdx.x; i < NB; i += blockDim.x) {
        unsigned char o;
        if (mode == 0)      o = (raw[i] != 0);
        else if (mode == 1) o = (((const int*)raw)[i] != 0);
        else                o = (((const float*)raw)[i] != 0.0f);
        g_inv[i] = o;
    }
}

// ---------------- 1x1 conv: f[b][o][s] = sum_c x[b][c][s]*w[o][c] + bias[o] ---
__global__ void k_conv(const float* __restrict__ x,
                       const float* __restrict__ w,
                       const float* __restrict__ bias) {
    __shared__ float xs[CIN];
    const int b = blockIdx.y, s = blockIdx.x;
    const int t = threadIdx.x;  // 64 threads, one per output channel
    for (int c = t; c < CIN; c += 64)
        xs[c] = x[(size_t)(b*CIN + c)*HW + s];
    __syncthreads();
    float acc = bias[t];
    const float4* wp = (const float4*)(w + (size_t)t*CIN);
#pragma unroll 8
    for (int c4 = 0; c4 < CIN/4; c4++) {
        float4 wv = wp[c4];
        acc += xs[4*c4+0]*wv.x + xs[4*c4+1]*wv.y + xs[4*c4+2]*wv.z + xs[4*c4+3]*wv.w;
    }
    g_f[(size_t)(b*AFC + t)*HW + s] = acc;
}

// ---------------- gather: feat[(b,p)][c*FH+h] = mask * f[b][c][h][cut_x[p][h]] -
__global__ void k_gather(const int* __restrict__ cut_x) {
    const int row = blockIdx.x;
    const int b = row / P, p = row - b*P;
    __shared__ int cx[FH];
    __shared__ unsigned char iv[FH];
    if (threadIdx.x < FH) {
        cx[threadIdx.x] = cut_x[p*FH + threadIdx.x];
        iv[threadIdx.x] = g_inv[p*FH + threadIdx.x];
    }
    __syncthreads();
    for (int d = threadIdx.x; d < DIM; d += blockDim.x) {
        int c = d / FH, h = d - c*FH;
        float v = iv[h] ? 0.0f : g_f[(size_t)(b*AFC + c)*HW + h*FW + cx[h]];
        g_feat[(size_t)row*DIM + d] = v;
    }
}

// ---------------- GEMM1: g_att[m][n] = feat[m][:] . att_w[n][:] + att_b[n] ----
// M=22272 (multiple of 128), N=2783 (guarded), K=704 (multiple of 16)
#define SPAD 132   // padded smem row: 132 % 32 = 4 -> conflict-free strided writes
__global__ __launch_bounds__(256) void k_gemm1(const float* __restrict__ Bw,
                                               const float* __restrict__ bias) {
    __shared__ float As[16][SPAD];
    __shared__ float Bs[16][SPAD];
    const int bm = blockIdx.y * 128, bn = blockIdx.x * 128;
    const int tid = threadIdx.x;
    const int ty = tid >> 4, tx = tid & 15;
    float acc[8][8];
#pragma unroll
    for (int i = 0; i < 8; i++)
#pragma unroll
        for (int j = 0; j < 8; j++) acc[i][j] = 0.0f;

    for (int k0 = 0; k0 < DIM; k0 += 16) {
#pragma unroll
        for (int q = 0; q < 2; q++) {
            int idx = tid + q*256;
            int r = idx >> 2, c4 = (idx & 3) << 2;
            float4 v = *(const float4*)(g_feat + (size_t)(bm + r)*DIM + k0 + c4);
            As[c4+0][r] = v.x; As[c4+1][r] = v.y; As[c4+2][r] = v.z; As[c4+3][r] = v.w;
            int n = bn + r;
            float4 u = make_float4(0.f, 0.f, 0.f, 0.f);
            if (n < PM1) u = *(const float4*)(Bw + (size_t)n*DIM + k0 + c4);
            Bs[c4+0][r] = u.x; Bs[c4+1][r] = u.y; Bs[c4+2][r] = u.z; Bs[c4+3][r] = u.w;
        }
        __syncthreads();
#pragma unroll
        for (int kk = 0; kk < 16; kk++) {
            float a[8], bb[8];
            *(float4*)(a)   = *(const float4*)&As[kk][ty*8];
            *(float4*)(a+4) = *(const float4*)&As[kk][ty*8+4];
            *(float4*)(bb)   = *(const float4*)&Bs[kk][tx*8];
            *(float4*)(bb+4) = *(const float4*)&Bs[kk][tx*8+4];
#pragma unroll
            for (int i = 0; i < 8; i++)
#pragma unroll
                for (int j = 0; j < 8; j++) acc[i][j] += a[i]*bb[j];
        }
        __syncthreads();
    }
#pragma unroll
    for (int i = 0; i < 8; i++) {
        int m = bm + ty*8 + i;
#pragma unroll
        for (int j = 0; j < 8; j++) {
            int n = bn + tx*8 + j;
            if (n < PM1) g_att[(size_t)m*PM1 + n] = acc[i][j] + bias[n];
        }
    }
}

// ---------------- softmax over rows of g_att (in place) ----------------------
__global__ void k_softmax() {
    __shared__ float srow[PM1];
    __shared__ float red[256];
    const size_t base = (size_t)blockIdx.x * PM1;
    const int t = threadIdx.x;
    float mx = -1e30f;
    for (int i = t; i < PM1; i += 256) {
        float v = g_att[base + i]; srow[i] = v; mx = fmaxf(mx, v);
    }
    red[t] = mx; __syncthreads();
    for (int s = 128; s > 0; s >>= 1) { if (t < s) red[t] = fmaxf(red[t], red[t+s]); __syncthreads(); }
    mx = red[0]; __syncthreads();
    float sum = 0.0f;
    for (int i = t; i < PM1; i += 256) {
        float e = __expf(srow[i] - mx); srow[i] = e; sum += e;
    }
    red[t] = sum; __syncthreads();
    for (int s = 128; s > 0; s >>= 1) { if (t < s) red[t] += red[t+s]; __syncthreads(); }
    float inv = 1.0f / red[0];
    for (int i = t; i < PM1; i += 256) g_att[base + i] = srow[i] * inv;
}

// ---------------- GEMM2: att_feat[b] = A_shifted[b] @ feat[b] ----------------
// A_shifted[m][k] = (k==m) ? 0 : att[b][m][k - (k>m)]  (fused in A-tile load)
// per batch: M=2784 (guard), N=704 (guard), K=2784 (multiple of 16)
__global__ __launch_bounds__(256) void k_gemm2() {
    __shared__ float As[16][SPAD];
    __shared__ float Bs[16][SPAD];
    const int b  = blockIdx.z;
    const int m0 = blockIdx.y * 128, n0 = blockIdx.x * 128;
    const int tid = threadIdx.x;
    const int ty = tid >> 4, tx = tid & 15;
    const float* attb  = g_att  + (size_t)b*P*PM1;
    const float* featb = g_feat + (size_t)b*P*DIM;
    float acc[8][8];
#pragma unroll
    for (int i = 0; i < 8; i++)
#pragma unroll
        for (int j = 0; j < 8; j++) acc[i][j] = 0.0f;

    for (int k0 = 0; k0 < P; k0 += 16) {
        // A tile with diagonal-skip gather (coalesced along k; SPAD kills the
        // 16-way bank conflict of the strided As[k][m] writes)
        for (int i = tid; i < 128*16; i += 256) {
            int m = i >> 4, k = i & 15;
            int gm = m0 + m, gk = k0 + k;
            float v = 0.0f;
            if (gm < P && gk != gm) {
                int j = gk - (gk > gm);
                v = attb[(size_t)gm*PM1 + j];
            }
            As[k][m] = v;
        }
        // B tile: feat rows (k), cols (n) — direct vector stage
#pragma unroll
        for (int q = 0; q < 2; q++) {
            int idx = tid + q*256;
            int kk = idx >> 5, c4 = (idx & 31) << 2;
            int n = n0 + c4;
            float4 u = make_float4(0.f, 0.f, 0.f, 0.f);
            if (n < DIM) u = *(const float4*)(featb + (size_t)(k0 + kk)*DIM + n);
            *(float4*)&Bs[kk][c4] = u;
        }
        __syncthreads();
#pragma unroll
        for (int kk = 0; kk < 16; kk++) {
            float a[8], bb[8];
            *(float4*)(a)   = *(const float4*)&As[kk][ty*8];
            *(float4*)(a+4) = *(const float4*)&As[kk][ty*8+4];
            *(float4*)(bb)   = *(const float4*)&Bs[kk][tx*8];
            *(float4*)(bb+4) = *(const float4*)&Bs[kk][tx*8+4];
#pragma unroll
            for (int i = 0; i < 8; i++)
#pragma unroll
                for (int j = 0; j < 8; j++) acc[i][j] += a[i]*bb[j];
        }
        __syncthreads();
    }
#pragma unroll
    for (int i = 0; i < 8; i++) {
        int m = m0 + ty*8 + i;
        if (m >= P) continue;
#pragma unroll
        for (int j = 0; j < 8; j++) {
            int n = n0 + tx*8 + j;
            if (n < DIM) g_attfeat[(size_t)(b*P + m)*DIM + n] = acc[i][j];
        }
    }
}

// ---------------- epilogue: [att_feat|feat] @ [cls_w;reg_w]^T + assembly -----
__global__ __launch_bounds__(256) void k_epi(const float* __restrict__ cls_w,
                                             const float* __restrict__ cls_b,
                                             const float* __restrict__ reg_w,
                                             const float* __restrict__ reg_b,
                                             const float* __restrict__ anchors,
                                             float* __restrict__ out) {
    __shared__ float As[16][SPAD];
    __shared__ float Ws[16][80];
    const int m0 = blockIdx.x * 128;
    const int tid = threadIdx.x;
    const int ty = tid >> 4, tx = tid & 15;
    float acc[8][5];
#pragma unroll
    for (int i = 0; i < 8; i++)
#pragma unroll
        for (int j = 0; j < 5; j++) acc[i][j] = 0.0f;

    for (int k0 = 0; k0 < DIM2; k0 += 16) {
#pragma unroll
        for (int q = 0; q < 2; q++) {
            int idx = tid + q*256;
            int r = idx >> 2, c4 = (idx & 3) << 2;
            int gk = k0 + c4;
            const float* src = (gk < DIM)
                ? (g_attfeat + (size_t)(m0 + r)*DIM + gk)
                : (g_feat    + (size_t)(m0 + r)*DIM + (gk - DIM));
            float4 v = *(const float4*)src;
            As[c4+0][r] = v.x; As[c4+1][r] = v.y; As[c4+2][r] = v.z; As[c4+3][r] = v.w;
        }
        for (int i = tid; i < 16*80; i += 256) {
            int kk = i / 80, n = i - kk*80;
            int gk = k0 + kk;
            float v = 0.0f;
            if (n < 2)          v = cls_w[(size_t)n*DIM2 + gk];
            else if (n < NWOUT) v = reg_w[(size_t)(n-2)*DIM2 + gk];
            Ws[kk][n] = v;
        }
        __syncthreads();
#pragma unroll
        for (int kk = 0; kk < 16; kk++) {
            float a[8], w[5];
            *(float4*)(a)   = *(const float4*)&As[kk][ty*8];
            *(float4*)(a+4) = *(const float4*)&As[kk][ty*8+4];
#pragma unroll
            for (int j = 0; j < 5; j++) w[j] = Ws[kk][tx*5 + j];
#pragma unroll
            for (int i = 0; i < 8; i++)
#pragma unroll
                for (int j = 0; j < 5; j++) acc[i][j] += a[i]*w[j];
        }
        __syncthreads();
    }
    // output layout: [reg_prop[...,2:] | start_y | start_x | cls_logits]
    const size_t O0 = 0;
    const size_t O1 = (size_t)M_TOT * 72;
    const size_t O2 = O1 + M_TOT;
    const size_t O3 = O2 + M_TOT;
#pragma unroll
    for (int i = 0; i < 8; i++) {
        int row = m0 + ty*8 + i;
        int bidx = row / P, p = row - bidx*P;
        (void)bidx;
#pragma unroll
        for (int j = 0; j < 5; j++) {
            int n = tx*5 + j;
            if (n >= NWOUT) continue;
            float r = acc[i][j] + (n < 2 ? cls_b[n] : reg_b[n-2]);
            if (n < 2) {
                out[O3 + (size_t)row*2 + n] = r;
            } else if (n == 2) {
                out[O2 + row] = anchors[p*74 + 1] + r;   // start_x + reg[...,0]
                out[O1 + row] = anchors[p*74 + 0];       // start_y (untouched)
            } else {
                out[O0 + (size_t)row*72 + (n-3)] = anchors[p*74 + 2 + (n-3)] + r;
            }
        }
    }
}

// ---------------- launch ----------------
extern "C" void kernel_launch(void* const* d_in, const int* in_sizes, int n_in,
                              void* d_out, int out_size) {
    const float* x       = (const float*)d_in[0];
    const float* conv_w  = (const float*)d_in[1];
    const float* conv_b  = (const float*)d_in[2];
    const float* att_w   = (const float*)d_in[3];
    const float* att_b   = (const float*)d_in[4];
    const float* cls_w   = (const float*)d_in[5];
    const float* cls_b   = (const float*)d_in[6];
    const float* reg_w   = (const float*)d_in[7];
    const float* reg_b   = (const float*)d_in[8];
    const float* anchors = (const float*)d_in[9];
    const int*   cut_x   = (const int*)d_in[10];
    const unsigned char* invalid = (const unsigned char*)d_in[11];
    float* out = (float*)d_out;
    (void)in_sizes; (void)n_in; (void)out_size;

    k_detect_inv<<<1, 1024>>>(invalid);
    k_conv<<<dim3(HW, BATCH), 64>>>(x, conv_w, conv_b);
    k_gather<<<M_TOT, 128>>>(cut_x);
    k_gemm1<<<dim3((PM1 + 127)/128, M_TOT/128), 256>>>(att_w, att_b);
    k_softmax<<<M_TOT, 256>>>();
    k_gemm2<<<dim3((DIM + 127)/128, (P + 127)/128, BATCH), 256>>>();
    k_epi<<<M_TOT/128, 256>>>(cls_w, cls_b, reg_w, reg_b, anchors, out);
}

// round 3
// speedup vs baseline: 1.9884x; 1.9884x over previous
#include <cuda_runtime.h>
#include <cstdint>
#include <cstddef>

// ---------------- problem constants ----------------
#define BATCH   8
#define P       2784
#define PM1     2783
#define FH      11
#define FW      20
#define HW      220        // FH*FW
#define CIN     512
#define AFC     64
#define DIM     704        // AFC*FH
#define DIM2    1408
#define NWOUT   75         // 2 cls + 73 reg
#define M_TOT   (BATCH*P)  // 22272  (divisible by 128: 174*128)

// ---------------- scratch (static device memory; no allocs allowed) ----------
__device__ float         g_f[BATCH*AFC*HW];                  // conv output
__device__ float         g_feat[(size_t)M_TOT*DIM];          // gathered features
__device__ float         g_att[(size_t)M_TOT*PM1];           // scores -> softmax (in place)
__device__ float         g_attfeat[(size_t)M_TOT*DIM];       // attention output
__device__ unsigned char g_inv[P*FH];                        // normalized invalid mask

// ---------------- tf32 helpers ----------------
__device__ __forceinline__ uint32_t f2tf32(float x) {
    uint32_t r; asm("cvt.rna.tf32.f32 %0, %1;" : "=r"(r) : "f"(x)); return r;
}
__device__ __forceinline__ void mma_tf32(float* c, const uint32_t* a, const uint32_t* b) {
    asm volatile("mma.sync.aligned.m16n8k8.row.col.f32.tf32.tf32.f32 "
                 "{%0,%1,%2,%3}, {%4,%5,%6,%7}, {%8,%9}, {%0,%1,%2,%3};"
                 : "+f"(c[0]), "+f"(c[1]), "+f"(c[2]), "+f"(c[3])
                 : "r"(a[0]), "r"(a[1]), "r"(a[2]), "r"(a[3]),
                   "r"(b[0]), "r"(b[1]));
}

// ---------------- invalid-dtype detection + normalization --------------------
__global__ void k_detect_inv(const unsigned char* __restrict__ raw) {
    __shared__ int f_gt1, f_mod;
    if (threadIdx.x == 0) { f_gt1 = 0; f_mod = 0; }
    __syncthreads();
    const int NB = P * FH;
    int lg = 0, lm = 0;
    for (int i = threadIdx.x; i < NB; i += blockDim.x) {
        unsigned char v = raw[i];
        if (v > 1) lg = 1;
        if (v != 0 && (i & 3) != 0) lm = 1;
    }
    if (lg) atomicOr(&f_gt1, 1);
    if (lm) atomicOr(&f_mod, 1);
    __syncthreads();
    int mode = f_gt1 ? 2 : (f_mod ? 0 : 1);   // 2=float32, 0=bool, 1=int32
    for (int i = threadIdx.x; i < NB; i += blockDim.x) {
        unsigned char o;
        if (mode == 0)      o = (raw[i] != 0);
        else if (mode == 1) o = (((const int*)raw)[i] != 0);
        else                o = (((const float*)raw)[i] != 0.0f);
        g_inv[i] = o;
    }
}

// ---------------- 1x1 conv ----------------
__global__ void k_conv(const float* __restrict__ x,
                       const float* __restrict__ w,
                       const float* __restrict__ bias) {
    __shared__ float xs[CIN];
    const int b = blockIdx.y, s = blockIdx.x;
    const int t = threadIdx.x;
    for (int c = t; c < CIN; c += 64)
        xs[c] = x[(size_t)(b*CIN + c)*HW + s];
    __syncthreads();
    float acc = bias[t];
    const float4* wp = (const float4*)(w + (size_t)t*CIN);
#pragma unroll 8
    for (int c4 = 0; c4 < CIN/4; c4++) {
        float4 wv = wp[c4];
        acc += xs[4*c4+0]*wv.x + xs[4*c4+1]*wv.y + xs[4*c4+2]*wv.z + xs[4*c4+3]*wv.w;
    }
    g_f[(size_t)(b*AFC + t)*HW + s] = acc;
}

// ---------------- gather ----------------
__global__ void k_gather(const int* __restrict__ cut_x) {
    const int row = blockIdx.x;
    const int b = row / P, p = row - b*P;
    __shared__ int cx[FH];
    __shared__ unsigned char iv[FH];
    if (threadIdx.x < FH) {
        cx[threadIdx.x] = cut_x[p*FH + threadIdx.x];
        iv[threadIdx.x] = g_inv[p*FH + threadIdx.x];
    }
    __syncthreads();
    for (int d = threadIdx.x; d < DIM; d += blockDim.x) {
        int c = d / FH, h = d - c*FH;
        float v = iv[h] ? 0.0f : g_f[(size_t)(b*AFC + c)*HW + h*FW + cx[h]];
        g_feat[(size_t)row*DIM + d] = v;
    }
}

// ============== GEMM1 (tensor core): g_att = feat @ att_w^T + bias ===========
// M=22272, N=2783 (guard), K=704. Block 128x128, Kstep 32, 8 warps (2x4),
// warp tile 64x32 = 4x4 m16n8k8 mma tiles.
// As [m][36] tf32, Bs [n][36] tf32 (att_w is [n][k] already = col-major B).
#define AK 36
__global__ __launch_bounds__(256) void k_gemm1_tc(const float* __restrict__ Bw,
                                                  const float* __restrict__ bias) {
    __shared__ uint32_t As[128*AK];
    __shared__ uint32_t Bs[128*AK];
    const int bm = blockIdx.y*128, bn = blockIdx.x*128;
    const int tid = threadIdx.x, lane = tid & 31, wid = tid >> 5;
    const int wm = (wid >> 2)*64, wn = (wid & 3)*32;
    const int g = lane >> 2, t4 = lane & 3;
    float acc[4][4][4];
#pragma unroll
    for (int i = 0; i < 4; i++)
#pragma unroll
        for (int j = 0; j < 4; j++)
#pragma unroll
            for (int r = 0; r < 4; r++) acc[i][j][r] = 0.0f;

    for (int k0 = 0; k0 < DIM; k0 += 32) {
#pragma unroll
        for (int q = 0; q < 4; q++) {
            int idx = tid + q*256;
            int r = idx >> 3, c = (idx & 7) << 2;
            float4 v = *(const float4*)(g_feat + (size_t)(bm + r)*DIM + k0 + c);
            uint4 tv = make_uint4(f2tf32(v.x), f2tf32(v.y), f2tf32(v.z), f2tf32(v.w));
            *(uint4*)&As[r*AK + c] = tv;
            int n = bn + r;
            float4 u = make_float4(0.f,0.f,0.f,0.f);
            if (n < PM1) u = *(const float4*)(Bw + (size_t)n*DIM + k0 + c);
            uint4 tu = make_uint4(f2tf32(u.x), f2tf32(u.y), f2tf32(u.z), f2tf32(u.w));
            *(uint4*)&Bs[r*AK + c] = tu;
        }
        __syncthreads();
#pragma unroll
        for (int kk = 0; kk < 32; kk += 8) {
            uint32_t af[4][4], bf[4][2];
#pragma unroll
            for (int mt = 0; mt < 4; mt++) {
                int row = wm + mt*16 + g;
                af[mt][0] = As[row*AK + kk + t4];
                af[mt][1] = As[(row+8)*AK + kk + t4];
                af[mt][2] = As[row*AK + kk + t4 + 4];
                af[mt][3] = As[(row+8)*AK + kk + t4 + 4];
            }
#pragma unroll
            for (int nt = 0; nt < 4; nt++) {
                int rn = wn + nt*8 + g;
                bf[nt][0] = Bs[rn*AK + kk + t4];
                bf[nt][1] = Bs[rn*AK + kk + t4 + 4];
            }
#pragma unroll
            for (int mt = 0; mt < 4; mt++)
#pragma unroll
                for (int nt = 0; nt < 4; nt++)
                    mma_tf32(acc[mt][nt], af[mt], bf[nt]);
        }
        __syncthreads();
    }
    // epilogue: c0 (g, t4*2), c1 (g, t4*2+1), c2 (g+8, ...), c3
#pragma unroll
    for (int mt = 0; mt < 4; mt++) {
        int r0 = bm + wm + mt*16 + g;
#pragma unroll
        for (int nt = 0; nt < 4; nt++) {
            int n0 = bn + wn + nt*8 + t4*2;
            if (n0 < PM1)     g_att[(size_t)r0*PM1 + n0]       = acc[mt][nt][0] + bias[n0];
            if (n0+1 < PM1)   g_att[(size_t)r0*PM1 + n0+1]     = acc[mt][nt][1] + bias[n0+1];
            if (n0 < PM1)     g_att[(size_t)(r0+8)*PM1 + n0]   = acc[mt][nt][2] + bias[n0];
            if (n0+1 < PM1)   g_att[(size_t)(r0+8)*PM1 + n0+1] = acc[mt][nt][3] + bias[n0+1];
        }
    }
}

// ---------------- softmax over rows of g_att (in place) ----------------------
__global__ void k_softmax() {
    __shared__ float srow[PM1];
    __shared__ float red[256];
    const size_t base = (size_t)blockIdx.x * PM1;
    const int t = threadIdx.x;
    float mx = -1e30f;
    for (int i = t; i < PM1; i += 256) {
        float v = g_att[base + i]; srow[i] = v; mx = fmaxf(mx, v);
    }
    red[t] = mx; __syncthreads();
    for (int s = 128; s > 0; s >>= 1) { if (t < s) red[t] = fmaxf(red[t], red[t+s]); __syncthreads(); }
    mx = red[0]; __syncthreads();
    float sum = 0.0f;
    for (int i = t; i < PM1; i += 256) {
        float e = __expf(srow[i] - mx); srow[i] = e; sum += e;
    }
    red[t] = sum; __syncthreads();
    for (int s = 128; s > 0; s >>= 1) { if (t < s) red[t] += red[t+s]; __syncthreads(); }
    float inv = 1.0f / red[0];
    for (int i = t; i < PM1; i += 256) g_att[base + i] = srow[i] * inv;
}

// ============== GEMM2 (tensor core): att_feat[b] = A_shifted[b] @ feat[b] ====
// A_shifted[m][k] = (k==m) ? 0 : att[b][m][k-(k>m)]  (fused into A staging).
// per batch: M=2784 (guard), N=704 (guard), K=2784 (exact /32).
// As [m][36] tf32; Bs [k][136] tf32 (feat is [k][n] row-major).
#define BN2 136
__global__ __launch_bounds__(256) void k_gemm2_tc() {
    __shared__ uint32_t As[128*AK];
    __shared__ uint32_t Bs[32*BN2];
    const int b  = blockIdx.z;
    const int m0 = blockIdx.y*128, n0 = blockIdx.x*128;
    const int tid = threadIdx.x, lane = tid & 31, wid = tid >> 5;
    const int wm = (wid >> 2)*64, wn = (wid & 3)*32;
    const int g = lane >> 2, t4 = lane & 3;
    const float* attb  = g_att  + (size_t)b*P*PM1;
    const float* featb = g_feat + (size_t)b*P*DIM;
    float acc[4][4][4];
#pragma unroll
    for (int i = 0; i < 4; i++)
#pragma unroll
        for (int j = 0; j < 4; j++)
#pragma unroll
            for (int r = 0; r < 4; r++) acc[i][j][r] = 0.0f;

    for (int k0 = 0; k0 < P; k0 += 32) {
        // A: diag-skip gather, scalar (coalesced along k), tf32 convert
#pragma unroll
        for (int q = 0; q < 16; q++) {
            int idx = tid + q*256;
            int m = idx >> 5, k = idx & 31;
            int gm = m0 + m, gk = k0 + k;
            float v = 0.0f;
            if (gm < P && gk != gm)
                v = attb[(size_t)gm*PM1 + gk - (gk > gm)];
            As[m*AK + k] = f2tf32(v);
        }
        // B: feat rows (k), cols (n)
#pragma unroll
        for (int q = 0; q < 4; q++) {
            int idx = tid + q*256;
            int kk = idx >> 5, c = (idx & 31) << 2;
            int n = n0 + c;
            float4 u = make_float4(0.f,0.f,0.f,0.f);
            if (n < DIM) u = *(const float4*)(featb + (size_t)(k0 + kk)*DIM + n);
            uint4 tu = make_uint4(f2tf32(u.x), f2tf32(u.y), f2tf32(u.z), f2tf32(u.w));
            *(uint4*)&Bs[kk*BN2 + c] = tu;
        }
        __syncthreads();
#pragma unroll
        for (int kk = 0; kk < 32; kk += 8) {
            uint32_t af[4][4], bf[4][2];
#pragma unroll
            for (int mt = 0; mt < 4; mt++) {
                int row = wm + mt*16 + g;
                af[mt][0] = As[row*AK + kk + t4];
                af[mt][1] = As[(row+8)*AK + kk + t4];
                af[mt][2] = As[row*AK + kk + t4 + 4];
                af[mt][3] = As[(row+8)*AK + kk + t4 + 4];
            }
#pragma unroll
            for (int nt = 0; nt < 4; nt++) {
                int cn = wn + nt*8 + g;
                bf[nt][0] = Bs[(kk + t4)*BN2 + cn];
                bf[nt][1] = Bs[(kk + t4 + 4)*BN2 + cn];
            }
#pragma unroll
            for (int mt = 0; mt < 4; mt++)
#pragma unroll
                for (int nt = 0; nt < 4; nt++)
                    mma_tf32(acc[mt][nt], af[mt], bf[nt]);
        }
        __syncthreads();
    }
#pragma unroll
    for (int mt = 0; mt < 4; mt++) {
        int r0 = m0 + wm + mt*16 + g;
#pragma unroll
        for (int nt = 0; nt < 4; nt++) {
            int n0c = n0 + wn + nt*8 + t4*2;
            if (r0 < P) {
                if (n0c < DIM)   g_attfeat[(size_t)(b*P + r0)*DIM + n0c]   = acc[mt][nt][0];
                if (n0c+1 < DIM) g_attfeat[(size_t)(b*P + r0)*DIM + n0c+1] = acc[mt][nt][1];
            }
            if (r0+8 < P) {
                if (n0c < DIM)   g_attfeat[(size_t)(b*P + r0+8)*DIM + n0c]   = acc[mt][nt][2];
                if (n0c+1 < DIM) g_attfeat[(size_t)(b*P + r0+8)*DIM + n0c+1] = acc[mt][nt][3];
            }
        }
    }
}

// ---------------- epilogue: [att_feat|feat] @ [cls_w;reg_w]^T + assembly -----
#define SPAD 132
__global__ __launch_bounds__(256) void k_epi(const float* __restrict__ cls_w,
                                             const float* __restrict__ cls_b,
                                             const float* __restrict__ reg_w,
                                             const float* __restrict__ reg_b,
                                             const float* __restrict__ anchors,
                                             float* __restrict__ out) {
    __shared__ float As2[16][SPAD];
    __shared__ float Ws[16][80];
    const int m0 = blockIdx.x * 128;
    const int tid = threadIdx.x;
    const int ty = tid >> 4, tx = tid & 15;
    float acc[8][5];
#pragma unroll
    for (int i = 0; i < 8; i++)
#pragma unroll
        for (int j = 0; j < 5; j++) acc[i][j] = 0.0f;

    for (int k0 = 0; k0 < DIM2; k0 += 16) {
#pragma unroll
        for (int q = 0; q < 2; q++) {
            int idx = tid + q*256;
            int r = idx >> 2, c4 = (idx & 3) << 2;
            int gk = k0 + c4;
            const float* src = (gk < DIM)
                ? (g_attfeat + (size_t)(m0 + r)*DIM + gk)
                : (g_feat    + (size_t)(m0 + r)*DIM + (gk - DIM));
            float4 v = *(const float4*)src;
            As2[c4+0][r] = v.x; As2[c4+1][r] = v.y; As2[c4+2][r] = v.z; As2[c4+3][r] = v.w;
        }
        for (int i = tid; i < 16*80; i += 256) {
            int kk = i / 80, n = i - kk*80;
            int gk = k0 + kk;
            float v = 0.0f;
            if (n < 2)          v = cls_w[(size_t)n*DIM2 + gk];
            else if (n < NWOUT) v = reg_w[(size_t)(n-2)*DIM2 + gk];
            Ws[kk][n] = v;
        }
        __syncthreads();
#pragma unroll
        for (int kk = 0; kk < 16; kk++) {
            float a[8], w[5];
            *(float4*)(a)   = *(const float4*)&As2[kk][ty*8];
            *(float4*)(a+4) = *(const float4*)&As2[kk][ty*8+4];
#pragma unroll
            for (int j = 0; j < 5; j++) w[j] = Ws[kk][tx*5 + j];
#pragma unroll
            for (int i = 0; i < 8; i++)
#pragma unroll
                for (int j = 0; j < 5; j++) acc[i][j] += a[i]*w[j];
        }
        __syncthreads();
    }
    const size_t O0 = 0;
    const size_t O1 = (size_t)M_TOT * 72;
    const size_t O2 = O1 + M_TOT;
    const size_t O3 = O2 + M_TOT;
#pragma unroll
    for (int i = 0; i < 8; i++) {
        int row = m0 + ty*8 + i;
        int bidx = row / P, p = row - bidx*P;
        (void)bidx;
#pragma unroll
        for (int j = 0; j < 5; j++) {
            int n = tx*5 + j;
            if (n >= NWOUT) continue;
            float r = acc[i][j] + (n < 2 ? cls_b[n] : reg_b[n-2]);
            if (n < 2) {
                out[O3 + (size_t)row*2 + n] = r;
            } else if (n == 2) {
                out[O2 + row] = anchors[p*74 + 1] + r;   // start_x + reg[...,0]
                out[O1 + row] = anchors[p*74 + 0];       // start_y
            } else {
                out[O0 + (size_t)row*72 + (n-3)] = anchors[p*74 + 2 + (n-3)] + r;
            }
        }
    }
}

// ---------------- launch ----------------
extern "C" void kernel_launch(void* const* d_in, const int* in_sizes, int n_in,
                              void* d_out, int out_size) {
    const float* x       = (const float*)d_in[0];
    const float* conv_w  = (const float*)d_in[1];
    const float* conv_b  = (const float*)d_in[2];
    const float* att_w   = (const float*)d_in[3];
    const float* att_b   = (const float*)d_in[4];
    const float* cls_w   = (const float*)d_in[5];
    const float* cls_b   = (const float*)d_in[6];
    const float* reg_w   = (const float*)d_in[7];
    const float* reg_b   = (const float*)d_in[8];
    const float* anchors = (const float*)d_in[9];
    const int*   cut_x   = (const int*)d_in[10];
    const unsigned char* invalid = (const unsigned char*)d_in[11];
    float* out = (float*)d_out;
    (void)in_sizes; (void)n_in; (void)out_size;

    k_detect_inv<<<1, 1024>>>(invalid);
    k_conv<<<dim3(HW, BATCH), 64>>>(x, conv_w, conv_b);
    k_gather<<<M_TOT, 128>>>(cut_x);
    k_gemm1_tc<<<dim3((PM1 + 127)/128, M_TOT/128), 256>>>(att_w, att_b);
    k_softmax<<<M_TOT, 256>>>();
    k_gemm2_tc<<<dim3((DIM + 127)/128, (P + 127)/128, BATCH), 256>>>();
    k_epi<<<M_TOT/128, 256>>>(cls_w, cls_b, reg_w, reg_b, anchors, out);
}

// round 4
// speedup vs baseline: 2.8985x; 1.4577x over previous
#include <cuda_runtime.h>
#include <cuda_bf16.h>
#include <cstdint>
#include <cstddef>

// ---------------- problem constants ----------------
#define BATCH   8
#define P       2784
#define PM1     2783
#define FH      11
#define FW      20
#define HW      220
#define CIN     512
#define AFC     64
#define DIM     704
#define DIM2    1408
#define NWOUT   75
#define M_TOT   (BATCH*P)   // 22272 = 174*128
#define AKH     40          // smem row pitch in halfs (32 data + 8 pad)
#define BN2     136         // gemm2 B smem pitch in u32 words

// ---------------- scratch ----------------
__device__ float          g_f[BATCH*AFC*HW];
__device__ float          g_feat[(size_t)M_TOT*DIM];          // fp32 feat (epi)
__device__ __nv_bfloat16  g_featb[(size_t)M_TOT*DIM];         // bf16 feat (gemms)
__device__ __nv_bfloat16  g_attwb[(size_t)PM1*DIM];           // bf16 att_w
__device__ float          g_att[(size_t)M_TOT*PM1];           // fp32 scores
__device__ __nv_bfloat16  g_attb[(size_t)M_TOT*PM1];          // bf16 softmax out
__device__ float          g_attfeat[(size_t)M_TOT*DIM];
__device__ unsigned char  g_inv[P*FH];

// ---------------- mma / cp.async helpers ----------------
__device__ __forceinline__ void mma_bf16(float* c, const uint32_t* a, const uint32_t* b) {
    asm volatile("mma.sync.aligned.m16n8k16.row.col.f32.bf16.bf16.f32 "
                 "{%0,%1,%2,%3}, {%4,%5,%6,%7}, {%8,%9}, {%0,%1,%2,%3};"
                 : "+f"(c[0]), "+f"(c[1]), "+f"(c[2]), "+f"(c[3])
                 : "r"(a[0]), "r"(a[1]), "r"(a[2]), "r"(a[3]),
                   "r"(b[0]), "r"(b[1]));
}
__device__ __forceinline__ void cpa16(uint32_t s, const void* g) {
    asm volatile("cp.async.cg.shared.global [%0], [%1], 16;" :: "r"(s), "l"(g));
}
__device__ __forceinline__ void cpa16p(uint32_t s, const void* g, int pred) {
    int sz = pred ? 16 : 0;
    asm volatile("cp.async.cg.shared.global [%0], [%1], 16, %2;" :: "r"(s), "l"(g), "r"(sz));
}
__device__ __forceinline__ uint32_t svta(const void* p) {
    return (uint32_t)__cvta_generic_to_shared(p);
}

// ---------------- invalid-dtype detection + normalization --------------------
__global__ void k_detect_inv(const unsigned char* __restrict__ raw) {
    __shared__ int f_gt1, f_mod;
    if (threadIdx.x == 0) { f_gt1 = 0; f_mod = 0; }
    __syncthreads();
    const int NB = P * FH;
    int lg = 0, lm = 0;
    for (int i = threadIdx.x; i < NB; i += blockDim.x) {
        unsigned char v = raw[i];
        if (v > 1) lg = 1;
        if (v != 0 && (i & 3) != 0) lm = 1;
    }
    if (lg) atomicOr(&f_gt1, 1);
    if (lm) atomicOr(&f_mod, 1);
    __syncthreads();
    int mode = f_gt1 ? 2 : (f_mod ? 0 : 1);
    for (int i = threadIdx.x; i < NB; i += blockDim.x) {
        unsigned char o;
        if (mode == 0)      o = (raw[i] != 0);
        else if (mode == 1) o = (((const int*)raw)[i] != 0);
        else                o = (((const float*)raw)[i] != 0.0f);
        g_inv[i] = o;
    }
}

// ---------------- 1x1 conv ----------------
__global__ void k_conv(const float* __restrict__ x,
                       const float* __restrict__ w,
                       const float* __restrict__ bias) {
    __shared__ float xs[CIN];
    const int b = blockIdx.y, s = blockIdx.x;
    const int t = threadIdx.x;
    for (int c = t; c < CIN; c += 64)
        xs[c] = x[(size_t)(b*CIN + c)*HW + s];
    __syncthreads();
    float acc = bias[t];
    const float4* wp = (const float4*)(w + (size_t)t*CIN);
#pragma unroll 8
    for (int c4 = 0; c4 < CIN/4; c4++) {
        float4 wv = wp[c4];
        acc += xs[4*c4+0]*wv.x + xs[4*c4+1]*wv.y + xs[4*c4+2]*wv.z + xs[4*c4+3]*wv.w;
    }
    g_f[(size_t)(b*AFC + t)*HW + s] = acc;
}

// ---------------- att_w -> bf16 ----------------
__global__ void k_cvt_attw(const float* __restrict__ w) {
    int i = blockIdx.x*256 + threadIdx.x;
    if (i < PM1*DIM) g_attwb[i] = __float2bfloat16(w[i]);
}

// ---------------- gather (fp32 + bf16 outputs) ----------------
__global__ void k_gather(const int* __restrict__ cut_x) {
    const int row = blockIdx.x;
    const int b = row / P, p = row - b*P;
    __shared__ int cx[FH];
    __shared__ unsigned char iv[FH];
    if (threadIdx.x < FH) {
        cx[threadIdx.x] = cut_x[p*FH + threadIdx.x];
        iv[threadIdx.x] = g_inv[p*FH + threadIdx.x];
    }
    __syncthreads();
    for (int d = threadIdx.x; d < DIM; d += blockDim.x) {
        int c = d / FH, h = d - c*FH;
        float v = iv[h] ? 0.0f : g_f[(size_t)(b*AFC + c)*HW + h*FW + cx[h]];
        g_feat[(size_t)row*DIM + d]  = v;
        g_featb[(size_t)row*DIM + d] = __float2bfloat16(v);
    }
}

// ============== GEMM1 (bf16 mma, cp.async double-buffered) ===================
// g_att[m][n] = featb[m][:] . attwb[n][:] + bias[n]
// M=22272, N=2783 (guard), K=704 (22 ksteps of 32)
__global__ __launch_bounds__(256) void k_gemm1_bf(const float* __restrict__ bias) {
    __shared__ __align__(16) __nv_bfloat16 As[2][128*AKH];
    __shared__ __align__(16) __nv_bfloat16 Bs[2][128*AKH];
    const int bm = blockIdx.y*128, bn = blockIdx.x*128;
    const int tid = threadIdx.x, lane = tid & 31, wid = tid >> 5;
    const int wm = (wid >> 2)*64, wn = (wid & 3)*32;
    const int g = lane >> 2, t4 = lane & 3;
    float acc[4][4][4];
#pragma unroll
    for (int i = 0; i < 4; i++)
#pragma unroll
        for (int j = 0; j < 4; j++)
#pragma unroll
            for (int r = 0; r < 4; r++) acc[i][j][r] = 0.0f;

    const int r_st  = tid >> 2;            // 0..63? no: tid>>2 is 0..63 for q=0
    const int c8_st = (tid & 3) * 8;

    auto stage = [&](int buf, int k0) {
#pragma unroll
        for (int q = 0; q < 2; q++) {
            int idx = tid + q*256;
            int r = idx >> 2, c8 = (idx & 3) << 3;
            cpa16(svta(&As[buf][r*AKH + c8]),
                  g_featb + (size_t)(bm + r)*DIM + k0 + c8);
            int n = bn + r;
            int ok = (n < PM1);
            cpa16p(svta(&Bs[buf][r*AKH + c8]),
                   g_attwb + (size_t)(ok ? n : 0)*DIM + k0 + c8, ok);
        }
    };
    (void)r_st; (void)c8_st;

    stage(0, 0);
    asm volatile("cp.async.commit_group;");
    int buf = 0;
    for (int it = 0; it < DIM/32; it++) {
        if (it + 1 < DIM/32) {
            stage(buf ^ 1, (it + 1)*32);
            asm volatile("cp.async.commit_group;");
            asm volatile("cp.async.wait_group 1;");
        } else {
            asm volatile("cp.async.wait_group 0;");
        }
        __syncthreads();
#pragma unroll
        for (int ks = 0; ks < 2; ks++) {
            const int kk = ks*16;
            uint32_t af[4][4], bf[4][2];
#pragma unroll
            for (int mt = 0; mt < 4; mt++) {
                int row = wm + mt*16 + g;
                af[mt][0] = *(const uint32_t*)&As[buf][row*AKH + kk + 2*t4];
                af[mt][1] = *(const uint32_t*)&As[buf][(row+8)*AKH + kk + 2*t4];
                af[mt][2] = *(const uint32_t*)&As[buf][row*AKH + kk + 8 + 2*t4];
                af[mt][3] = *(const uint32_t*)&As[buf][(row+8)*AKH + kk + 8 + 2*t4];
            }
#pragma unroll
            for (int nt = 0; nt < 4; nt++) {
                int rn = wn + nt*8 + g;
                bf[nt][0] = *(const uint32_t*)&Bs[buf][rn*AKH + kk + 2*t4];
                bf[nt][1] = *(const uint32_t*)&Bs[buf][rn*AKH + kk + 8 + 2*t4];
            }
#pragma unroll
            for (int mt = 0; mt < 4; mt++)
#pragma unroll
                for (int nt = 0; nt < 4; nt++)
                    mma_bf16(acc[mt][nt], af[mt], bf[nt]);
        }
        __syncthreads();
        buf ^= 1;
    }
#pragma unroll
    for (int mt = 0; mt < 4; mt++) {
        int r0 = bm + wm + mt*16 + g;
#pragma unroll
        for (int nt = 0; nt < 4; nt++) {
            int n0 = bn + wn + nt*8 + t4*2;
            if (n0 < PM1)   g_att[(size_t)r0*PM1 + n0]       = acc[mt][nt][0] + bias[n0];
            if (n0+1 < PM1) g_att[(size_t)r0*PM1 + n0+1]     = acc[mt][nt][1] + bias[n0+1];
            if (n0 < PM1)   g_att[(size_t)(r0+8)*PM1 + n0]   = acc[mt][nt][2] + bias[n0];
            if (n0+1 < PM1) g_att[(size_t)(r0+8)*PM1 + n0+1] = acc[mt][nt][3] + bias[n0+1];
        }
    }
}

// ---------------- softmax (fp32 in, bf16 out) --------------------------------
__global__ void k_softmax() {
    __shared__ float srow[PM1];
    __shared__ float red[256];
    const size_t base = (size_t)blockIdx.x * PM1;
    const int t = threadIdx.x;
    float mx = -1e30f;
    for (int i = t; i < PM1; i += 256) {
        float v = g_att[base + i]; srow[i] = v; mx = fmaxf(mx, v);
    }
    red[t] = mx; __syncthreads();
    for (int s = 128; s > 0; s >>= 1) { if (t < s) red[t] = fmaxf(red[t], red[t+s]); __syncthreads(); }
    mx = red[0]; __syncthreads();
    float sum = 0.0f;
    for (int i = t; i < PM1; i += 256) {
        float e = __expf(srow[i] - mx); srow[i] = e; sum += e;
    }
    red[t] = sum; __syncthreads();
    for (int s = 128; s > 0; s >>= 1) { if (t < s) red[t] += red[t+s]; __syncthreads(); }
    float inv = 1.0f / red[0];
    for (int i = t; i < PM1; i += 256) g_attb[base + i] = __float2bfloat16(srow[i] * inv);
}

// ============== GEMM2 (bf16 mma, fused diag-skip gather) =====================
// att_feat[b] = A_shifted[b] @ featb[b];  A_shifted[m][k] = (k==m)?0:attb[m][k-(k>m)]
// per batch: M=2784 (guard), N=704 (guard), K=2784 (87 ksteps of 32)
__global__ __launch_bounds__(256) void k_gemm2_bf() {
    __shared__ __align__(16) __nv_bfloat16 As[128*AKH];
    __shared__ __align__(16) uint32_t Bs2[16*BN2];   // (k-pair, n) interleaved bf16x2
    const int b  = blockIdx.z;
    const int m0 = blockIdx.y*128, n0 = blockIdx.x*128;
    const int tid = threadIdx.x, lane = tid & 31, wid = tid >> 5;
    const int wm = (wid >> 2)*64, wn = (wid & 3)*32;
    const int g = lane >> 2, t4 = lane & 3;
    const __nv_bfloat16* attb  = g_attb  + (size_t)b*P*PM1;
    const __nv_bfloat16* featb = g_featb + (size_t)b*P*DIM;
    float acc[4][4][4];
#pragma unroll
    for (int i = 0; i < 4; i++)
#pragma unroll
        for (int j = 0; j < 4; j++)
#pragma unroll
            for (int r = 0; r < 4; r++) acc[i][j][r] = 0.0f;

    const __nv_bfloat16 zero = __float2bfloat16(0.0f);
    for (int k0 = 0; k0 < P; k0 += 32) {
        // A: diag-skip gather (warp covers 32 consecutive k of one m row)
#pragma unroll
        for (int q = 0; q < 16; q++) {
            int idx = tid + q*256;
            int m = idx >> 5, k = idx & 31;
            int gm = m0 + m, gk = k0 + k;
            __nv_bfloat16 v = zero;
            if (gm < P && gk != gm)
                v = attb[(size_t)gm*PM1 + gk - (gk > gm)];
            As[m*AKH + k] = v;
        }
        // B: interleave k-pairs -> Bs2[k2][n] = (feat[2k2][n], feat[2k2+1][n])
#pragma unroll
        for (int q = 0; q < 2; q++) {
            int idx = tid + q*256;
            int k2 = idx >> 5, n4 = idx & 31;
            int n = n0 + n4*4;
            uint4 w = make_uint4(0u, 0u, 0u, 0u);
            if (n < DIM) {
                ushort4 va = *(const ushort4*)(featb + (size_t)(k0 + 2*k2)*DIM + n);
                ushort4 vb = *(const ushort4*)(featb + (size_t)(k0 + 2*k2 + 1)*DIM + n);
                w.x = (uint32_t)va.x | ((uint32_t)vb.x << 16);
                w.y = (uint32_t)va.y | ((uint32_t)vb.y << 16);
                w.z = (uint32_t)va.z | ((uint32_t)vb.z << 16);
                w.w = (uint32_t)va.w | ((uint32_t)vb.w << 16);
            }
            *(uint4*)&Bs2[k2*BN2 + n4*4] = w;
        }
        __syncthreads();
#pragma unroll
        for (int ks = 0; ks < 2; ks++) {
            const int kk = ks*16, kk2 = ks*8;
            uint32_t af[4][4], bf[4][2];
#pragma unroll
            for (int mt = 0; mt < 4; mt++) {
                int row = wm + mt*16 + g;
                af[mt][0] = *(const uint32_t*)&As[row*AKH + kk + 2*t4];
                af[mt][1] = *(const uint32_t*)&As[(row+8)*AKH + kk + 2*t4];
                af[mt][2] = *(const uint32_t*)&As[row*AKH + kk + 8 + 2*t4];
                af[mt][3] = *(const uint32_t*)&As[(row+8)*AKH + kk + 8 + 2*t4];
            }
#pragma unroll
            for (int nt = 0; nt < 4; nt++) {
                int cn = wn + nt*8 + g;
                bf[nt][0] = Bs2[(kk2 + t4)*BN2 + cn];
                bf[nt][1] = Bs2[(kk2 + 4 + t4)*BN2 + cn];
            }
#pragma unroll
            for (int mt = 0; mt < 4; mt++)
#pragma unroll
                for (int nt = 0; nt < 4; nt++)
                    mma_bf16(acc[mt][nt], af[mt], bf[nt]);
        }
        __syncthreads();
    }
#pragma unroll
    for (int mt = 0; mt < 4; mt++) {
        int r0 = m0 + wm + mt*16 + g;
#pragma unroll
        for (int nt = 0; nt < 4; nt++) {
            int n0c = n0 + wn + nt*8 + t4*2;
            if (r0 < P && n0c < DIM) {
                g_attfeat[(size_t)(b*P + r0)*DIM + n0c]   = acc[mt][nt][0];
                g_attfeat[(size_t)(b*P + r0)*DIM + n0c+1] = acc[mt][nt][1];
            }
            if (r0+8 < P && n0c < DIM) {
                g_attfeat[(size_t)(b*P + r0+8)*DIM + n0c]   = acc[mt][nt][2];
                g_attfeat[(size_t)(b*P + r0+8)*DIM + n0c+1] = acc[mt][nt][3];
            }
        }
    }
}

// ---------------- epilogue (fp32): [att_feat|feat] @ W^T + assembly ----------
#define SPAD 132
__global__ __launch_bounds__(256) void k_epi(const float* __restrict__ cls_w,
                                             const float* __restrict__ cls_b,
                                             const float* __restrict__ reg_w,
                                             const float* __restrict__ reg_b,
                                             const float* __restrict__ anchors,
                                             float* __restrict__ out) {
    __shared__ float As2[16][SPAD];
    __shared__ float Ws[16][80];
    const int m0 = blockIdx.x * 128;
    const int tid = threadIdx.x;
    const int ty = tid >> 4, tx = tid & 15;
    float acc[8][5];
#pragma unroll
    for (int i = 0; i < 8; i++)
#pragma unroll
        for (int j = 0; j < 5; j++) acc[i][j] = 0.0f;

    for (int k0 = 0; k0 < DIM2; k0 += 16) {
#pragma unroll
        for (int q = 0; q < 2; q++) {
            int idx = tid + q*256;
            int r = idx >> 2, c4 = (idx & 3) << 2;
            int gk = k0 + c4;
            const float* src = (gk < DIM)
                ? (g_attfeat + (size_t)(m0 + r)*DIM + gk)
                : (g_feat    + (size_t)(m0 + r)*DIM + (gk - DIM));
            float4 v = *(const float4*)src;
            As2[c4+0][r] = v.x; As2[c4+1][r] = v.y; As2[c4+2][r] = v.z; As2[c4+3][r] = v.w;
        }
        for (int i = tid; i < 16*80; i += 256) {
            int kk = i / 80, n = i - kk*80;
            int gk = k0 + kk;
            float v = 0.0f;
            if (n < 2)          v = cls_w[(size_t)n*DIM2 + gk];
            else if (n < NWOUT) v = reg_w[(size_t)(n-2)*DIM2 + gk];
            Ws[kk][n] = v;
        }
        __syncthreads();
#pragma unroll
        for (int kk = 0; kk < 16; kk++) {
            float a[8], w[5];
            *(float4*)(a)   = *(const float4*)&As2[kk][ty*8];
            *(float4*)(a+4) = *(const float4*)&As2[kk][ty*8+4];
#pragma unroll
            for (int j = 0; j < 5; j++) w[j] = Ws[kk][tx*5 + j];
#pragma unroll
            for (int i = 0; i < 8; i++)
#pragma unroll
                for (int j = 0; j < 5; j++) acc[i][j] += a[i]*w[j];
        }
        __syncthreads();
    }
    const size_t O0 = 0;
    const size_t O1 = (size_t)M_TOT * 72;
    const size_t O2 = O1 + M_TOT;
    const size_t O3 = O2 + M_TOT;
#pragma unroll
    for (int i = 0; i < 8; i++) {
        int row = m0 + ty*8 + i;
        int bidx = row / P, p = row - bidx*P;
        (void)bidx;
#pragma unroll
        for (int j = 0; j < 5; j++) {
            int n = tx*5 + j;
            if (n >= NWOUT) continue;
            float r = acc[i][j] + (n < 2 ? cls_b[n] : reg_b[n-2]);
            if (n < 2) {
                out[O3 + (size_t)row*2 + n] = r;
            } else if (n == 2) {
                out[O2 + row] = anchors[p*74 + 1] + r;
                out[O1 + row] = anchors[p*74 + 0];
            } else {
                out[O0 + (size_t)row*72 + (n-3)] = anchors[p*74 + 2 + (n-3)] + r;
            }
        }
    }
}

// ---------------- launch ----------------
extern "C" void kernel_launch(void* const* d_in, const int* in_sizes, int n_in,
                              void* d_out, int out_size) {
    const float* x       = (const float*)d_in[0];
    const float* conv_w  = (const float*)d_in[1];
    const float* conv_b  = (const float*)d_in[2];
    const float* att_w   = (const float*)d_in[3];
    const float* att_b   = (const float*)d_in[4];
    const float* cls_w   = (const float*)d_in[5];
    const float* cls_b   = (const float*)d_in[6];
    const float* reg_w   = (const float*)d_in[7];
    const float* reg_b   = (const float*)d_in[8];
    const float* anchors = (const float*)d_in[9];
    const int*   cut_x   = (const int*)d_in[10];
    const unsigned char* invalid = (const unsigned char*)d_in[11];
    float* out = (float*)d_out;
    (void)in_sizes; (void)n_in; (void)out_size;

    k_detect_inv<<<1, 1024>>>(invalid);
    k_conv<<<dim3(HW, BATCH), 64>>>(x, conv_w, conv_b);
    k_cvt_attw<<<(PM1*DIM + 255)/256, 256>>>(att_w);
    k_gather<<<M_TOT, 128>>>(cut_x);
    k_gemm1_bf<<<dim3((PM1 + 127)/128, M_TOT/128), 256>>>(att_b);
    k_softmax<<<M_TOT, 256>>>();
    k_gemm2_bf<<<dim3((DIM + 127)/128, (P + 127)/128, BATCH), 256>>>();
    k_epi<<<M_TOT/128, 256>>>(cls_w, cls_b, reg_w, reg_b, anchors, out);
}

// round 5
// speedup vs baseline: 4.1661x; 1.4374x over previous
#include <cuda_runtime.h>
#include <cuda_bf16.h>
#include <cstdint>
#include <cstddef>

// ---------------- problem constants ----------------
#define BATCH   8
#define P       2784
#define PM1     2783
#define FH      11
#define FW      20
#define HW      220
#define CIN     512
#define AFC     64
#define DIM     704
#define DIM2    1408
#define NWOUT   75
#define M_TOT   (BATCH*P)   // 22272 = 174*128
#define AKH     40          // smem row pitch in halfs (32 data + 8 pad)
#define BN2     136         // gemm2 B smem pitch in u32 words

// ---------------- scratch ----------------
__device__ float          g_f[BATCH*AFC*HW];
__device__ float          g_feat[(size_t)M_TOT*DIM];          // fp32 feat (epi)
__device__ __nv_bfloat16  g_featb[(size_t)M_TOT*DIM];         // bf16 feat (gemms)
__device__ __nv_bfloat16  g_attwb[(size_t)PM1*DIM];           // bf16 att_w
__device__ float          g_att[(size_t)M_TOT*PM1];           // fp32 scores
__device__ __nv_bfloat16  g_attsh[(size_t)M_TOT*P];           // bf16 SHIFTED softmax (dense PxP rows)
__device__ float          g_attfeat[(size_t)M_TOT*DIM];
__device__ unsigned char  g_inv[P*FH];

// ---------------- mma / cp.async helpers ----------------
__device__ __forceinline__ void mma_bf16(float* c, const uint32_t* a, const uint32_t* b) {
    asm volatile("mma.sync.aligned.m16n8k16.row.col.f32.bf16.bf16.f32 "
                 "{%0,%1,%2,%3}, {%4,%5,%6,%7}, {%8,%9}, {%0,%1,%2,%3};"
                 : "+f"(c[0]), "+f"(c[1]), "+f"(c[2]), "+f"(c[3])
                 : "r"(a[0]), "r"(a[1]), "r"(a[2]), "r"(a[3]),
                   "r"(b[0]), "r"(b[1]));
}
__device__ __forceinline__ void cpa16(uint32_t s, const void* g) {
    asm volatile("cp.async.cg.shared.global [%0], [%1], 16;" :: "r"(s), "l"(g));
}
__device__ __forceinline__ void cpa16p(uint32_t s, const void* g, int pred) {
    int sz = pred ? 16 : 0;
    asm volatile("cp.async.cg.shared.global [%0], [%1], 16, %2;" :: "r"(s), "l"(g), "r"(sz));
}
__device__ __forceinline__ uint32_t svta(const void* p) {
    return (uint32_t)__cvta_generic_to_shared(p);
}

// ---------------- invalid-dtype detection + normalization --------------------
__global__ void k_detect_inv(const unsigned char* __restrict__ raw) {
    __shared__ int f_gt1, f_mod;
    if (threadIdx.x == 0) { f_gt1 = 0; f_mod = 0; }
    __syncthreads();
    const int NB = P * FH;
    int lg = 0, lm = 0;
    for (int i = threadIdx.x; i < NB; i += blockDim.x) {
        unsigned char v = raw[i];
        if (v > 1) lg = 1;
        if (v != 0 && (i & 3) != 0) lm = 1;
    }
    if (lg) atomicOr(&f_gt1, 1);
    if (lm) atomicOr(&f_mod, 1);
    __syncthreads();
    int mode = f_gt1 ? 2 : (f_mod ? 0 : 1);
    for (int i = threadIdx.x; i < NB; i += blockDim.x) {
        unsigned char o;
        if (mode == 0)      o = (raw[i] != 0);
        else if (mode == 1) o = (((const int*)raw)[i] != 0);
        else                o = (((const float*)raw)[i] != 0.0f);
        g_inv[i] = o;
    }
}

// ---------------- 1x1 conv ----------------
__global__ void k_conv(const float* __restrict__ x,
                       const float* __restrict__ w,
                       const float* __restrict__ bias) {
    __shared__ float xs[CIN];
    const int b = blockIdx.y, s = blockIdx.x;
    const int t = threadIdx.x;
    for (int c = t; c < CIN; c += 64)
        xs[c] = x[(size_t)(b*CIN + c)*HW + s];
    __syncthreads();
    float acc = bias[t];
    const float4* wp = (const float4*)(w + (size_t)t*CIN);
#pragma unroll 8
    for (int c4 = 0; c4 < CIN/4; c4++) {
        float4 wv = wp[c4];
        acc += xs[4*c4+0]*wv.x + xs[4*c4+1]*wv.y + xs[4*c4+2]*wv.z + xs[4*c4+3]*wv.w;
    }
    g_f[(size_t)(b*AFC + t)*HW + s] = acc;
}

// ---------------- att_w -> bf16 ----------------
__global__ void k_cvt_attw(const float* __restrict__ w) {
    int i = blockIdx.x*256 + threadIdx.x;
    if (i < PM1*DIM) g_attwb[i] = __float2bfloat16(w[i]);
}

// ---------------- gather (fp32 + bf16 outputs) ----------------
__global__ void k_gather(const int* __restrict__ cut_x) {
    const int row = blockIdx.x;
    const int b = row / P, p = row - b*P;
    __shared__ int cx[FH];
    __shared__ unsigned char iv[FH];
    if (threadIdx.x < FH) {
        cx[threadIdx.x] = cut_x[p*FH + threadIdx.x];
        iv[threadIdx.x] = g_inv[p*FH + threadIdx.x];
    }
    __syncthreads();
    for (int d = threadIdx.x; d < DIM; d += blockDim.x) {
        int c = d / FH, h = d - c*FH;
        float v = iv[h] ? 0.0f : g_f[(size_t)(b*AFC + c)*HW + h*FW + cx[h]];
        g_feat[(size_t)row*DIM + d]  = v;
        g_featb[(size_t)row*DIM + d] = __float2bfloat16(v);
    }
}

// ============== GEMM1 (bf16 mma, cp.async double-buffered) ===================
// g_att[m][n] = featb[m][:] . attwb[n][:] + bias[n]
__global__ __launch_bounds__(256) void k_gemm1_bf(const float* __restrict__ bias) {
    __shared__ __align__(16) __nv_bfloat16 As[2][128*AKH];
    __shared__ __align__(16) __nv_bfloat16 Bs[2][128*AKH];
    const int bm = blockIdx.y*128, bn = blockIdx.x*128;
    const int tid = threadIdx.x, lane = tid & 31, wid = tid >> 5;
    const int wm = (wid >> 2)*64, wn = (wid & 3)*32;
    const int g = lane >> 2, t4 = lane & 3;
    float acc[4][4][4];
#pragma unroll
    for (int i = 0; i < 4; i++)
#pragma unroll
        for (int j = 0; j < 4; j++)
#pragma unroll
            for (int r = 0; r < 4; r++) acc[i][j][r] = 0.0f;

    auto stage = [&](int buf, int k0) {
#pragma unroll
        for (int q = 0; q < 2; q++) {
            int idx = tid + q*256;
            int r = idx >> 2, c8 = (idx & 3) << 3;
            cpa16(svta(&As[buf][r*AKH + c8]),
                  g_featb + (size_t)(bm + r)*DIM + k0 + c8);
            int n = bn + r;
            int ok = (n < PM1);
            cpa16p(svta(&Bs[buf][r*AKH + c8]),
                   g_attwb + (size_t)(ok ? n : 0)*DIM + k0 + c8, ok);
        }
    };

    stage(0, 0);
    asm volatile("cp.async.commit_group;");
    int buf = 0;
    for (int it = 0; it < DIM/32; it++) {
        if (it + 1 < DIM/32) {
            stage(buf ^ 1, (it + 1)*32);
            asm volatile("cp.async.commit_group;");
            asm volatile("cp.async.wait_group 1;");
        } else {
            asm volatile("cp.async.wait_group 0;");
        }
        __syncthreads();
#pragma unroll
        for (int ks = 0; ks < 2; ks++) {
            const int kk = ks*16;
            uint32_t af[4][4], bf[4][2];
#pragma unroll
            for (int mt = 0; mt < 4; mt++) {
                int row = wm + mt*16 + g;
                af[mt][0] = *(const uint32_t*)&As[buf][row*AKH + kk + 2*t4];
                af[mt][1] = *(const uint32_t*)&As[buf][(row+8)*AKH + kk + 2*t4];
                af[mt][2] = *(const uint32_t*)&As[buf][row*AKH + kk + 8 + 2*t4];
                af[mt][3] = *(const uint32_t*)&As[buf][(row+8)*AKH + kk + 8 + 2*t4];
            }
#pragma unroll
            for (int nt = 0; nt < 4; nt++) {
                int rn = wn + nt*8 + g;
                bf[nt][0] = *(const uint32_t*)&Bs[buf][rn*AKH + kk + 2*t4];
                bf[nt][1] = *(const uint32_t*)&Bs[buf][rn*AKH + kk + 8 + 2*t4];
            }
#pragma unroll
            for (int mt = 0; mt < 4; mt++)
#pragma unroll
                for (int nt = 0; nt < 4; nt++)
                    mma_bf16(acc[mt][nt], af[mt], bf[nt]);
        }
        __syncthreads();
        buf ^= 1;
    }
#pragma unroll
    for (int mt = 0; mt < 4; mt++) {
        int r0 = bm + wm + mt*16 + g;
#pragma unroll
        for (int nt = 0; nt < 4; nt++) {
            int n0 = bn + wn + nt*8 + t4*2;
            if (n0 < PM1)   g_att[(size_t)r0*PM1 + n0]       = acc[mt][nt][0] + bias[n0];
            if (n0+1 < PM1) g_att[(size_t)r0*PM1 + n0+1]     = acc[mt][nt][1] + bias[n0+1];
            if (n0 < PM1)   g_att[(size_t)(r0+8)*PM1 + n0]   = acc[mt][nt][2] + bias[n0];
            if (n0+1 < PM1) g_att[(size_t)(r0+8)*PM1 + n0+1] = acc[mt][nt][3] + bias[n0+1];
        }
    }
}

// ---------------- softmax: fp32 in, bf16 SHIFTED dense row out ---------------
// g_attsh[row][k] = (k==m) ? 0 : softmax(scores[row])[k - (k>m)]
__global__ void k_softmax() {
    __shared__ float srow[PM1];
    __shared__ float red[256];
    const size_t base  = (size_t)blockIdx.x * PM1;
    const size_t obase = (size_t)blockIdx.x * P;
    const int m = blockIdx.x % P;           // position within batch -> diagonal
    const int t = threadIdx.x;
    float mx = -1e30f;
    for (int i = t; i < PM1; i += 256) {
        float v = g_att[base + i]; srow[i] = v; mx = fmaxf(mx, v);
    }
    red[t] = mx; __syncthreads();
    for (int s = 128; s > 0; s >>= 1) { if (t < s) red[t] = fmaxf(red[t], red[t+s]); __syncthreads(); }
    mx = red[0]; __syncthreads();
    float sum = 0.0f;
    for (int i = t; i < PM1; i += 256) {
        float e = __expf(srow[i] - mx); srow[i] = e; sum += e;
    }
    red[t] = sum; __syncthreads();
    for (int s = 128; s > 0; s >>= 1) { if (t < s) red[t] += red[t+s]; __syncthreads(); }
    float inv = 1.0f / red[0];
    for (int i = t; i < PM1; i += 256)
        g_attsh[obase + i + (i >= m)] = __float2bfloat16(srow[i] * inv);
    if (t == 0) g_attsh[obase + m] = __float2bfloat16(0.0f);
}

// ============== GEMM2 (bf16 mma, cp.async double-buffered) ===================
// att_feat[b] = A_shift[b] @ featb[b];  A_shift is the dense pre-shifted matrix.
// per batch: M=2784 (guard), N=704 (guard), K=2784 (87 ksteps of 32)
__global__ __launch_bounds__(256) void k_gemm2_bf() {
    __shared__ __align__(16) __nv_bfloat16 As[2][128*AKH];
    __shared__ __align__(16) uint32_t Bs2[2][16*BN2];   // (k-pair, n) interleaved bf16x2
    const int b  = blockIdx.z;
    const int m0 = blockIdx.y*128, n0 = blockIdx.x*128;
    const int tid = threadIdx.x, lane = tid & 31, wid = tid >> 5;
    const int wm = (wid >> 2)*64, wn = (wid & 3)*32;
    const int g = lane >> 2, t4 = lane & 3;
    const __nv_bfloat16* attsh = g_attsh + (size_t)b*P*P;
    const __nv_bfloat16* featb = g_featb + (size_t)b*P*DIM;
    float acc[4][4][4];
#pragma unroll
    for (int i = 0; i < 4; i++)
#pragma unroll
        for (int j = 0; j < 4; j++)
#pragma unroll
            for (int r = 0; r < 4; r++) acc[i][j][r] = 0.0f;

    auto stageA = [&](int buf, int k0) {
#pragma unroll
        for (int q = 0; q < 2; q++) {
            int idx = tid + q*256;
            int r = idx >> 2, c8 = (idx & 3) << 3;
            int gm = m0 + r;
            int ok = (gm < P);
            cpa16p(svta(&As[buf][r*AKH + c8]),
                   attsh + (size_t)(ok ? gm : 0)*P + k0 + c8, ok);
        }
    };
    auto stageB = [&](int buf, int k0) {
#pragma unroll
        for (int q = 0; q < 2; q++) {
            int idx = tid + q*256;
            int k2 = idx >> 5, n4 = idx & 31;
            int n = n0 + n4*4;
            uint4 w = make_uint4(0u, 0u, 0u, 0u);
            if (n < DIM) {
                ushort4 va = *(const ushort4*)(featb + (size_t)(k0 + 2*k2)*DIM + n);
                ushort4 vb = *(const ushort4*)(featb + (size_t)(k0 + 2*k2 + 1)*DIM + n);
                w.x = (uint32_t)va.x | ((uint32_t)vb.x << 16);
                w.y = (uint32_t)va.y | ((uint32_t)vb.y << 16);
                w.z = (uint32_t)va.z | ((uint32_t)vb.z << 16);
                w.w = (uint32_t)va.w | ((uint32_t)vb.w << 16);
            }
            *(uint4*)&Bs2[buf][k2*BN2 + n4*4] = w;
        }
    };

    stageA(0, 0);
    asm volatile("cp.async.commit_group;");
    stageB(0, 0);
    int buf = 0;
    const int NK = P/32;   // 87
    for (int it = 0; it < NK; it++) {
        if (it + 1 < NK) {
            stageA(buf ^ 1, (it + 1)*32);
            asm volatile("cp.async.commit_group;");
            stageB(buf ^ 1, (it + 1)*32);
            asm volatile("cp.async.wait_group 1;");
        } else {
            asm volatile("cp.async.wait_group 0;");
        }
        __syncthreads();
#pragma unroll
        for (int ks = 0; ks < 2; ks++) {
            const int kk = ks*16, kk2 = ks*8;
            uint32_t af[4][4], bf[4][2];
#pragma unroll
            for (int mt = 0; mt < 4; mt++) {
                int row = wm + mt*16 + g;
                af[mt][0] = *(const uint32_t*)&As[buf][row*AKH + kk + 2*t4];
                af[mt][1] = *(const uint32_t*)&As[buf][(row+8)*AKH + kk + 2*t4];
                af[mt][2] = *(const uint32_t*)&As[buf][row*AKH + kk + 8 + 2*t4];
                af[mt][3] = *(const uint32_t*)&As[buf][(row+8)*AKH + kk + 8 + 2*t4];
            }
#pragma unroll
            for (int nt = 0; nt < 4; nt++) {
                int cn = wn + nt*8 + g;
                bf[nt][0] = Bs2[buf][(kk2 + t4)*BN2 + cn];
                bf[nt][1] = Bs2[buf][(kk2 + 4 + t4)*BN2 + cn];
            }
#pragma unroll
            for (int mt = 0; mt < 4; mt++)
#pragma unroll
                for (int nt = 0; nt < 4; nt++)
                    mma_bf16(acc[mt][nt], af[mt], bf[nt]);
        }
        __syncthreads();
        buf ^= 1;
    }
#pragma unroll
    for (int mt = 0; mt < 4; mt++) {
        int r0 = m0 + wm + mt*16 + g;
#pragma unroll
        for (int nt = 0; nt < 4; nt++) {
            int n0c = n0 + wn + nt*8 + t4*2;
            if (r0 < P && n0c < DIM) {
                g_attfeat[(size_t)(b*P + r0)*DIM + n0c]   = acc[mt][nt][0];
                g_attfeat[(size_t)(b*P + r0)*DIM + n0c+1] = acc[mt][nt][1];
            }
            if (r0+8 < P && n0c < DIM) {
                g_attfeat[(size_t)(b*P + r0+8)*DIM + n0c]   = acc[mt][nt][2];
                g_attfeat[(size_t)(b*P + r0+8)*DIM + n0c+1] = acc[mt][nt][3];
            }
        }
    }
}

// ---------------- epilogue (fp32): [att_feat|feat] @ W^T + assembly ----------
#define SPAD 132
__global__ __launch_bounds__(256) void k_epi(const float* __restrict__ cls_w,
                                             const float* __restrict__ cls_b,
                                             const float* __restrict__ reg_w,
                                             const float* __restrict__ reg_b,
                                             const float* __restrict__ anchors,
                                             float* __restrict__ out) {
    __shared__ float As2[16][SPAD];
    __shared__ float Ws[16][80];
    const int m0 = blockIdx.x * 128;
    const int tid = threadIdx.x;
    const int ty = tid >> 4, tx = tid & 15;
    float acc[8][5];
#pragma unroll
    for (int i = 0; i < 8; i++)
#pragma unroll
        for (int j = 0; j < 5; j++) acc[i][j] = 0.0f;

    for (int k0 = 0; k0 < DIM2; k0 += 16) {
#pragma unroll
        for (int q = 0; q < 2; q++) {
            int idx = tid + q*256;
            int r = idx >> 2, c4 = (idx & 3) << 2;
            int gk = k0 + c4;
            const float* src = (gk < DIM)
                ? (g_attfeat + (size_t)(m0 + r)*DIM + gk)
                : (g_feat    + (size_t)(m0 + r)*DIM + (gk - DIM));
            float4 v = *(const float4*)src;
            As2[c4+0][r] = v.x; As2[c4+1][r] = v.y; As2[c4+2][r] = v.z; As2[c4+3][r] = v.w;
        }
        for (int i = tid; i < 16*80; i += 256) {
            int kk = i / 80, n = i - kk*80;
            int gk = k0 + kk;
            float v = 0.0f;
            if (n < 2)          v = cls_w[(size_t)n*DIM2 + gk];
            else if (n < NWOUT) v = reg_w[(size_t)(n-2)*DIM2 + gk];
            Ws[kk][n] = v;
        }
        __syncthreads();
#pragma unroll
        for (int kk = 0; kk < 16; kk++) {
            float a[8], w[5];
            *(float4*)(a)   = *(const float4*)&As2[kk][ty*8];
            *(float4*)(a+4) = *(const float4*)&As2[kk][ty*8+4];
#pragma unroll
            for (int j = 0; j < 5; j++) w[j] = Ws[kk][tx*5 + j];
#pragma unroll
            for (int i = 0; i < 8; i++)
#pragma unroll
                for (int j = 0; j < 5; j++) acc[i][j] += a[i]*w[j];
        }
        __syncthreads();
    }
    const size_t O0 = 0;
    const size_t O1 = (size_t)M_TOT * 72;
    const size_t O2 = O1 + M_TOT;
    const size_t O3 = O2 + M_TOT;
#pragma unroll
    for (int i = 0; i < 8; i++) {
        int row = m0 + ty*8 + i;
        int bidx = row / P, p = row - bidx*P;
        (void)bidx;
#pragma unroll
        for (int j = 0; j < 5; j++) {
            int n = tx*5 + j;
            if (n >= NWOUT) continue;
            float r = acc[i][j] + (n < 2 ? cls_b[n] : reg_b[n-2]);
            if (n < 2) {
                out[O3 + (size_t)row*2 + n] = r;
            } else if (n == 2) {
                out[O2 + row] = anchors[p*74 + 1] + r;
                out[O1 + row] = anchors[p*74 + 0];
            } else {
                out[O0 + (size_t)row*72 + (n-3)] = anchors[p*74 + 2 + (n-3)] + r;
            }
        }
    }
}

// ---------------- launch ----------------
extern "C" void kernel_launch(void* const* d_in, const int* in_sizes, int n_in,
                              void* d_out, int out_size) {
    const float* x       = (const float*)d_in[0];
    const float* conv_w  = (const float*)d_in[1];
    const float* conv_b  = (const float*)d_in[2];
    const float* att_w   = (const float*)d_in[3];
    const float* att_b   = (const float*)d_in[4];
    const float* cls_w   = (const float*)d_in[5];
    const float* cls_b   = (const float*)d_in[6];
    const float* reg_w   = (const float*)d_in[7];
    const float* reg_b   = (const float*)d_in[8];
    const float* anchors = (const float*)d_in[9];
    const int*   cut_x   = (const int*)d_in[10];
    const unsigned char* invalid = (const unsigned char*)d_in[11];
    float* out = (float*)d_out;
    (void)in_sizes; (void)n_in; (void)out_size;

    k_detect_inv<<<1, 1024>>>(invalid);
    k_conv<<<dim3(HW, BATCH), 64>>>(x, conv_w, conv_b);
    k_cvt_attw<<<(PM1*DIM + 255)/256, 256>>>(att_w);
    k_gather<<<M_TOT, 128>>>(cut_x);
    k_gemm1_bf<<<dim3((PM1 + 127)/128, M_TOT/128), 256>>>(att_b);
    k_softmax<<<M_TOT, 256>>>();
    k_gemm2_bf<<<dim3((DIM + 127)/128, (P + 127)/128, BATCH), 256>>>();
    k_epi<<<M_TOT/128, 256>>>(cls_w, cls_b, reg_w, reg_b, anchors, out);
}

// round 6
// speedup vs baseline: 4.3031x; 1.0329x over previous
#include <cuda_runtime.h>
#include <cuda_bf16.h>
#include <cstdint>
#include <cstddef>

// ---------------- problem constants ----------------
#define BATCH   8
#define P       2784
#define PM1     2783
#define FH      11
#define FW      20
#define HW      220
#define CIN     512
#define AFC     64
#define DIM     704
#define DIM2    1408
#define NWOUT   75
#define M_TOT   (BATCH*P)   // 22272 = 174*128
#define AKH     40          // k-major smem pitch in halfs (32 data + 8 pad)
#define BNH     136         // gemm2 B (n-major) smem pitch in halfs (128 + 8 pad)

// ---------------- scratch ----------------
__device__ float          g_f[BATCH*AFC*HW];
__device__ float          g_feat[(size_t)M_TOT*DIM];          // fp32 feat (epi)
__device__ __nv_bfloat16  g_featb[(size_t)M_TOT*DIM];         // bf16 feat (gemms)
__device__ __nv_bfloat16  g_attwb[(size_t)PM1*DIM];           // bf16 att_w
__device__ float          g_att[(size_t)M_TOT*PM1];           // fp32 scores
__device__ __nv_bfloat16  g_attsh[(size_t)M_TOT*P];           // bf16 SHIFTED softmax (dense PxP)
__device__ float          g_attfeat[(size_t)M_TOT*DIM];
__device__ unsigned char  g_inv[P*FH];

// ---------------- mma / cp.async / ldmatrix helpers ----------------
__device__ __forceinline__ void mma_bf16(float* c, const uint32_t* a, const uint32_t* b) {
    asm volatile("mma.sync.aligned.m16n8k16.row.col.f32.bf16.bf16.f32 "
                 "{%0,%1,%2,%3}, {%4,%5,%6,%7}, {%8,%9}, {%0,%1,%2,%3};"
                 : "+f"(c[0]), "+f"(c[1]), "+f"(c[2]), "+f"(c[3])
                 : "r"(a[0]), "r"(a[1]), "r"(a[2]), "r"(a[3]),
                   "r"(b[0]), "r"(b[1]));
}
__device__ __forceinline__ void cpa16(uint32_t s, const void* g) {
    asm volatile("cp.async.cg.shared.global [%0], [%1], 16;" :: "r"(s), "l"(g));
}
__device__ __forceinline__ void cpa16p(uint32_t s, const void* g, int pred) {
    int sz = pred ? 16 : 0;
    asm volatile("cp.async.cg.shared.global [%0], [%1], 16, %2;" :: "r"(s), "l"(g), "r"(sz));
}
__device__ __forceinline__ uint32_t svta(const void* p) {
    return (uint32_t)__cvta_generic_to_shared(p);
}
__device__ __forceinline__ void ldsm4(uint32_t* r, uint32_t a) {
    asm volatile("ldmatrix.sync.aligned.m8n8.x4.shared.b16 {%0,%1,%2,%3}, [%4];"
                 : "=r"(r[0]), "=r"(r[1]), "=r"(r[2]), "=r"(r[3]) : "r"(a));
}
__device__ __forceinline__ void ldsm4t(uint32_t* r, uint32_t a) {
    asm volatile("ldmatrix.sync.aligned.m8n8.x4.trans.shared.b16 {%0,%1,%2,%3}, [%4];"
                 : "=r"(r[0]), "=r"(r[1]), "=r"(r[2]), "=r"(r[3]) : "r"(a));
}

// ---------------- invalid-dtype detection + normalization --------------------
__global__ void k_detect_inv(const unsigned char* __restrict__ raw) {
    __shared__ int f_gt1, f_mod;
    if (threadIdx.x == 0) { f_gt1 = 0; f_mod = 0; }
    __syncthreads();
    const int NB = P * FH;
    int lg = 0, lm = 0;
    for (int i = threadIdx.x; i < NB; i += blockDim.x) {
        unsigned char v = raw[i];
        if (v > 1) lg = 1;
        if (v != 0 && (i & 3) != 0) lm = 1;
    }
    if (lg) atomicOr(&f_gt1, 1);
    if (lm) atomicOr(&f_mod, 1);
    __syncthreads();
    int mode = f_gt1 ? 2 : (f_mod ? 0 : 1);
    for (int i = threadIdx.x; i < NB; i += blockDim.x) {
        unsigned char o;
        if (mode == 0)      o = (raw[i] != 0);
        else if (mode == 1) o = (((const int*)raw)[i] != 0);
        else                o = (((const float*)raw)[i] != 0.0f);
        g_inv[i] = o;
    }
}

// ---------------- 1x1 conv ----------------
__global__ void k_conv(const float* __restrict__ x,
                       const float* __restrict__ w,
                       const float* __restrict__ bias) {
    __shared__ float xs[CIN];
    const int b = blockIdx.y, s = blockIdx.x;
    const int t = threadIdx.x;
    for (int c = t; c < CIN; c += 64)
        xs[c] = x[(size_t)(b*CIN + c)*HW + s];
    __syncthreads();
    float acc = bias[t];
    const float4* wp = (const float4*)(w + (size_t)t*CIN);
#pragma unroll 8
    for (int c4 = 0; c4 < CIN/4; c4++) {
        float4 wv = wp[c4];
        acc += xs[4*c4+0]*wv.x + xs[4*c4+1]*wv.y + xs[4*c4+2]*wv.z + xs[4*c4+3]*wv.w;
    }
    g_f[(size_t)(b*AFC + t)*HW + s] = acc;
}

// ---------------- att_w -> bf16 ----------------
__global__ void k_cvt_attw(const float* __restrict__ w) {
    int i = blockIdx.x*256 + threadIdx.x;
    if (i < PM1*DIM) g_attwb[i] = __float2bfloat16(w[i]);
}

// ---------------- gather (fp32 + bf16 outputs) ----------------
__global__ void k_gather(const int* __restrict__ cut_x) {
    const int row = blockIdx.x;
    const int b = row / P, p = row - b*P;
    __shared__ int cx[FH];
    __shared__ unsigned char iv[FH];
    if (threadIdx.x < FH) {
        cx[threadIdx.x] = cut_x[p*FH + threadIdx.x];
        iv[threadIdx.x] = g_inv[p*FH + threadIdx.x];
    }
    __syncthreads();
    for (int d = threadIdx.x; d < DIM; d += blockDim.x) {
        int c = d / FH, h = d - c*FH;
        float v = iv[h] ? 0.0f : g_f[(size_t)(b*AFC + c)*HW + h*FW + cx[h]];
        g_feat[(size_t)row*DIM + d]  = v;
        g_featb[(size_t)row*DIM + d] = __float2bfloat16(v);
    }
}

// ============== GEMM1 (bf16 mma + ldmatrix, cp.async double-buffered) ========
// g_att[m][n] = featb[m][:] . attwb[n][:] + bias[n]
__global__ __launch_bounds__(256) void k_gemm1_bf(const float* __restrict__ bias) {
    __shared__ __align__(16) __nv_bfloat16 As[2][128*AKH];
    __shared__ __align__(16) __nv_bfloat16 Bs[2][128*AKH];
    const int bm = blockIdx.y*128, bn = blockIdx.x*128;
    const int tid = threadIdx.x, lane = tid & 31, wid = tid >> 5;
    const int wm = (wid >> 2)*64, wn = (wid & 3)*32;
    const int g = lane >> 2, t4 = lane & 3;
    float acc[4][4][4];
#pragma unroll
    for (int i = 0; i < 4; i++)
#pragma unroll
        for (int j = 0; j < 4; j++)
#pragma unroll
            for (int r = 0; r < 4; r++) acc[i][j][r] = 0.0f;

    // ldmatrix lane offsets (halfs)
    const int a_off = (wm + (lane & 7) + 8*((lane >> 3) & 1))*AKH + 8*(lane >> 4);
    const int b_off = (wn + (lane & 7) + 8*(lane >> 4))*AKH + 8*((lane >> 3) & 1);
    const uint32_t AsB[2] = { svta(&As[0][0]), svta(&As[1][0]) };
    const uint32_t BsB[2] = { svta(&Bs[0][0]), svta(&Bs[1][0]) };

    auto stage = [&](int buf, int k0) {
#pragma unroll
        for (int q = 0; q < 2; q++) {
            int idx = tid + q*256;
            int r = idx >> 2, c8 = (idx & 3) << 3;
            cpa16(svta(&As[buf][r*AKH + c8]),
                  g_featb + (size_t)(bm + r)*DIM + k0 + c8);
            int n = bn + r;
            int ok = (n < PM1);
            cpa16p(svta(&Bs[buf][r*AKH + c8]),
                   g_attwb + (size_t)(ok ? n : 0)*DIM + k0 + c8, ok);
        }
    };

    stage(0, 0);
    asm volatile("cp.async.commit_group;");
    int buf = 0;
    for (int it = 0; it < DIM/32; it++) {
        if (it + 1 < DIM/32) {
            stage(buf ^ 1, (it + 1)*32);
            asm volatile("cp.async.commit_group;");
            asm volatile("cp.async.wait_group 1;");
        } else {
            asm volatile("cp.async.wait_group 0;");
        }
        __syncthreads();
#pragma unroll
        for (int ks = 0; ks < 2; ks++) {
            const int kk = ks*16;
            uint32_t af[4][4], bq[2][4];
#pragma unroll
            for (int mt = 0; mt < 4; mt++)
                ldsm4(af[mt], AsB[buf] + 2*(a_off + mt*16*AKH + kk));
#pragma unroll
            for (int ntp = 0; ntp < 2; ntp++)
                ldsm4(bq[ntp], BsB[buf] + 2*(b_off + ntp*16*AKH + kk));
#pragma unroll
            for (int mt = 0; mt < 4; mt++)
#pragma unroll
                for (int nt = 0; nt < 4; nt++)
                    mma_bf16(acc[mt][nt], af[mt], &bq[nt >> 1][(nt & 1)*2]);
        }
        __syncthreads();
        buf ^= 1;
    }
#pragma unroll
    for (int mt = 0; mt < 4; mt++) {
        int r0 = bm + wm + mt*16 + g;
#pragma unroll
        for (int nt = 0; nt < 4; nt++) {
            int n0 = bn + wn + nt*8 + t4*2;
            if (n0 < PM1)   g_att[(size_t)r0*PM1 + n0]       = acc[mt][nt][0] + bias[n0];
            if (n0+1 < PM1) g_att[(size_t)r0*PM1 + n0+1]     = acc[mt][nt][1] + bias[n0+1];
            if (n0 < PM1)   g_att[(size_t)(r0+8)*PM1 + n0]   = acc[mt][nt][2] + bias[n0];
            if (n0+1 < PM1) g_att[(size_t)(r0+8)*PM1 + n0+1] = acc[mt][nt][3] + bias[n0+1];
        }
    }
}

// ---------------- softmax: fp32 in, bf16 SHIFTED dense row out ---------------
__global__ void k_softmax() {
    __shared__ float srow[PM1];
    __shared__ float red[256];
    const size_t base  = (size_t)blockIdx.x * PM1;
    const size_t obase = (size_t)blockIdx.x * P;
    const int m = blockIdx.x % P;
    const int t = threadIdx.x;
    float mx = -1e30f;
    for (int i = t; i < PM1; i += 256) {
        float v = g_att[base + i]; srow[i] = v; mx = fmaxf(mx, v);
    }
    red[t] = mx; __syncthreads();
    for (int s = 128; s > 0; s >>= 1) { if (t < s) red[t] = fmaxf(red[t], red[t+s]); __syncthreads(); }
    mx = red[0]; __syncthreads();
    float sum = 0.0f;
    for (int i = t; i < PM1; i += 256) {
        float e = __expf(srow[i] - mx); srow[i] = e; sum += e;
    }
    red[t] = sum; __syncthreads();
    for (int s = 128; s > 0; s >>= 1) { if (t < s) red[t] += red[t+s]; __syncthreads(); }
    float inv = 1.0f / red[0];
    for (int i = t; i < PM1; i += 256)
        g_attsh[obase + i + (i >= m)] = __float2bfloat16(srow[i] * inv);
    if (t == 0) g_attsh[obase + m] = __float2bfloat16(0.0f);
}

// ============== GEMM2 (bf16 mma + ldmatrix[.trans], cp.async x2-buffered) ====
// att_feat[b] = A_shift[b] @ featb[b]; B staged raw (k-major), trans in LDSM.
__global__ __launch_bounds__(256) void k_gemm2_bf() {
    __shared__ __align__(16) __nv_bfloat16 As[2][128*AKH];
    __shared__ __align__(16) __nv_bfloat16 Bs[2][32*BNH];
    const int b  = blockIdx.z;
    const int m0 = blockIdx.y*128, n0 = blockIdx.x*128;
    const int tid = threadIdx.x, lane = tid & 31, wid = tid >> 5;
    const int wm = (wid >> 2)*64, wn = (wid & 3)*32;
    const int g = lane >> 2, t4 = lane & 3;
    const __nv_bfloat16* attsh = g_attsh + (size_t)b*P*P;
    const __nv_bfloat16* featb = g_featb + (size_t)b*P*DIM;
    float acc[4][4][4];
#pragma unroll
    for (int i = 0; i < 4; i++)
#pragma unroll
        for (int j = 0; j < 4; j++)
#pragma unroll
            for (int r = 0; r < 4; r++) acc[i][j][r] = 0.0f;

    const int a_off  = (wm + (lane & 7) + 8*((lane >> 3) & 1))*AKH + 8*(lane >> 4);
    const int bt_off = ((lane & 7) + 8*((lane >> 3) & 1))*BNH + wn + 8*(lane >> 4);
    const uint32_t AsB[2] = { svta(&As[0][0]), svta(&As[1][0]) };
    const uint32_t BsB[2] = { svta(&Bs[0][0]), svta(&Bs[1][0]) };

    auto stage = [&](int buf, int k0) {
#pragma unroll
        for (int q = 0; q < 2; q++) {
            int idx = tid + q*256;
            int r = idx >> 2, c8 = (idx & 3) << 3;
            int gm = m0 + r;
            int ok = (gm < P);
            cpa16p(svta(&As[buf][r*AKH + c8]),
                   attsh + (size_t)(ok ? gm : 0)*P + k0 + c8, ok);
        }
#pragma unroll
        for (int q = 0; q < 2; q++) {
            int idx = tid + q*256;
            int kr = idx >> 4, c8 = (idx & 15) << 3;
            int n = n0 + c8;
            int ok = (n < DIM);
            cpa16p(svta(&Bs[buf][kr*BNH + c8]),
                   featb + (size_t)(k0 + kr)*DIM + (ok ? n : 0), ok);
        }
    };

    stage(0, 0);
    asm volatile("cp.async.commit_group;");
    int buf = 0;
    const int NK = P/32;   // 87
    for (int it = 0; it < NK; it++) {
        if (it + 1 < NK) {
            stage(buf ^ 1, (it + 1)*32);
            asm volatile("cp.async.commit_group;");
            asm volatile("cp.async.wait_group 1;");
        } else {
            asm volatile("cp.async.wait_group 0;");
        }
        __syncthreads();
#pragma unroll
        for (int ks = 0; ks < 2; ks++) {
            const int kk = ks*16;
            uint32_t af[4][4], bq[2][4];
#pragma unroll
            for (int mt = 0; mt < 4; mt++)
                ldsm4(af[mt], AsB[buf] + 2*(a_off + mt*16*AKH + kk));
#pragma unroll
            for (int ntp = 0; ntp < 2; ntp++)
                ldsm4t(bq[ntp], BsB[buf] + 2*(bt_off + kk*BNH + ntp*16));
#pragma unroll
            for (int mt = 0; mt < 4; mt++)
#pragma unroll
                for (int nt = 0; nt < 4; nt++)
                    mma_bf16(acc[mt][nt], af[mt], &bq[nt >> 1][(nt & 1)*2]);
        }
        __syncthreads();
        buf ^= 1;
    }
#pragma unroll
    for (int mt = 0; mt < 4; mt++) {
        int r0 = m0 + wm + mt*16 + g;
#pragma unroll
        for (int nt = 0; nt < 4; nt++) {
            int n0c = n0 + wn + nt*8 + t4*2;
            if (r0 < P && n0c < DIM) {
                g_attfeat[(size_t)(b*P + r0)*DIM + n0c]   = acc[mt][nt][0];
                g_attfeat[(size_t)(b*P + r0)*DIM + n0c+1] = acc[mt][nt][1];
            }
            if (r0+8 < P && n0c < DIM) {
                g_attfeat[(size_t)(b*P + r0+8)*DIM + n0c]   = acc[mt][nt][2];
                g_attfeat[(size_t)(b*P + r0+8)*DIM + n0c+1] = acc[mt][nt][3];
            }
        }
    }
}

// ---------------- epilogue (fp32): [att_feat|feat] @ W^T + assembly ----------
#define SPAD 132
__global__ __launch_bounds__(256) void k_epi(const float* __restrict__ cls_w,
                                             const float* __restrict__ cls_b,
                                             const float* __restrict__ reg_w,
                                             const float* __restrict__ reg_b,
                                             const float* __restrict__ anchors,
                                             float* __restrict__ out) {
    __shared__ float As2[16][SPAD];
    __shared__ float Ws[16][80];
    const int m0 = blockIdx.x * 128;
    const int tid = threadIdx.x;
    const int ty = tid >> 4, tx = tid & 15;
    float acc[8][5];
#pragma unroll
    for (int i = 0; i < 8; i++)
#pragma unroll
        for (int j = 0; j < 5; j++) acc[i][j] = 0.0f;

    for (int k0 = 0; k0 < DIM2; k0 += 16) {
#pragma unroll
        for (int q = 0; q < 2; q++) {
            int idx = tid + q*256;
            int r = idx >> 2, c4 = (idx & 3) << 2;
            int gk = k0 + c4;
            const float* src = (gk < DIM)
                ? (g_attfeat + (size_t)(m0 + r)*DIM + gk)
                : (g_feat    + (size_t)(m0 + r)*DIM + (gk - DIM));
            float4 v = *(const float4*)src;
            As2[c4+0][r] = v.x; As2[c4+1][r] = v.y; As2[c4+2][r] = v.z; As2[c4+3][r] = v.w;
        }
        for (int i = tid; i < 16*80; i += 256) {
            int kk = i / 80, n = i - kk*80;
            int gk = k0 + kk;
            float v = 0.0f;
            if (n < 2)          v = cls_w[(size_t)n*DIM2 + gk];
            else if (n < NWOUT) v = reg_w[(size_t)(n-2)*DIM2 + gk];
            Ws[kk][n] = v;
        }
        __syncthreads();
#pragma unroll
        for (int kk = 0; kk < 16; kk++) {
            float a[8], w[5];
            *(float4*)(a)   = *(const float4*)&As2[kk][ty*8];
            *(float4*)(a+4) = *(const float4*)&As2[kk][ty*8+4];
#pragma unroll
            for (int j = 0; j < 5; j++) w[j] = Ws[kk][tx*5 + j];
#pragma unroll
            for (int i = 0; i < 8; i++)
#pragma unroll
                for (int j = 0; j < 5; j++) acc[i][j] += a[i]*w[j];
        }
        __syncthreads();
    }
    const size_t O0 = 0;
    const size_t O1 = (size_t)M_TOT * 72;
    const size_t O2 = O1 + M_TOT;
    const size_t O3 = O2 + M_TOT;
#pragma unroll
    for (int i = 0; i < 8; i++) {
        int row = m0 + ty*8 + i;
        int bidx = row / P, p = row - bidx*P;
        (void)bidx;
#pragma unroll
        for (int j = 0; j < 5; j++) {
            int n = tx*5 + j;
            if (n >= NWOUT) continue;
            float r = acc[i][j] + (n < 2 ? cls_b[n] : reg_b[n-2]);
            if (n < 2) {
                out[O3 + (size_t)row*2 + n] = r;
            } else if (n == 2) {
                out[O2 + row] = anchors[p*74 + 1] + r;
                out[O1 + row] = anchors[p*74 + 0];
            } else {
                out[O0 + (size_t)row*72 + (n-3)] = anchors[p*74 + 2 + (n-3)] + r;
            }
        }
    }
}

// ---------------- launch ----------------
extern "C" void kernel_launch(void* const* d_in, const int* in_sizes, int n_in,
                              void* d_out, int out_size) {
    const float* x       = (const float*)d_in[0];
    const float* conv_w  = (const float*)d_in[1];
    const float* conv_b  = (const float*)d_in[2];
    const float* att_w   = (const float*)d_in[3];
    const float* att_b   = (const float*)d_in[4];
    const float* cls_w   = (const float*)d_in[5];
    const float* cls_b   = (const float*)d_in[6];
    const float* reg_w   = (const float*)d_in[7];
    const float* reg_b   = (const float*)d_in[8];
    const float* anchors = (const float*)d_in[9];
    const int*   cut_x   = (const int*)d_in[10];
    const unsigned char* invalid = (const unsigned char*)d_in[11];
    float* out = (float*)d_out;
    (void)in_sizes; (void)n_in; (void)out_size;

    k_detect_inv<<<1, 1024>>>(invalid);
    k_conv<<<dim3(HW, BATCH), 64>>>(x, conv_w, conv_b);
    k_cvt_attw<<<(PM1*DIM + 255)/256, 256>>>(att_w);
    k_gather<<<M_TOT, 128>>>(cut_x);
    k_gemm1_bf<<<dim3((PM1 + 127)/128, M_TOT/128), 256>>>(att_b);
    k_softmax<<<M_TOT, 256>>>();
    k_gemm2_bf<<<dim3((DIM + 127)/128, (P + 127)/128, BATCH), 256>>>();
    k_epi<<<M_TOT/128, 256>>>(cls_w, cls_b, reg_w, reg_b, anchors, out);
}

// round 8
// speedup vs baseline: 4.3562x; 1.0123x over previous
#include <cuda_runtime.h>
#include <cuda_bf16.h>
#include <cstdint>
#include <cstddef>

// ---------------- problem constants ----------------
#define BATCH   8
#define P       2784
#define PM1     2783
#define FH      11
#define FW      20
#define HW      220
#define CIN     512
#define AFC     64
#define DIM     704
#define DIM2    1408
#define NWOUT   75
#define M_TOT   (BATCH*P)   // 22272 = 174*128
#define AKH     40          // bf16 k-major smem pitch in halfs (32 data + 8 pad)
#define BNH     136         // gemm2 B (n-major) smem pitch in halfs (128 + 8 pad)
#define AP8     80          // fp8 smem pitch in bytes (64 data + 16 pad)
#define FEAT_SCALE 64.0f
#define ATTW_SCALE 256.0f
#define SCORE_INV  (1.0f/16384.0f)

// ---------------- scratch ----------------
__device__ float          g_f[BATCH*AFC*HW];
__device__ float          g_feat[(size_t)M_TOT*DIM];          // fp32 feat (epi)
__device__ __nv_bfloat16  g_featb[(size_t)M_TOT*DIM];         // bf16 feat (gemm2)
__device__ unsigned char  g_feat8[(size_t)M_TOT*DIM];         // e4m3 feat*64 (gemm1)
__device__ unsigned char  g_attw8[(size_t)PM1*DIM];           // e4m3 att_w*256 (gemm1)
__device__ float          g_att[(size_t)M_TOT*PM1];           // fp32 scores
__device__ __nv_bfloat16  g_attsh[(size_t)M_TOT*P];           // bf16 SHIFTED softmax (dense PxP)
__device__ float          g_attfeat[(size_t)M_TOT*DIM];
__device__ unsigned char  g_inv[P*FH];

// ---------------- helpers ----------------
__device__ __forceinline__ void mma_bf16(float* c, const uint32_t* a, const uint32_t* b) {
    asm volatile("mma.sync.aligned.m16n8k16.row.col.f32.bf16.bf16.f32 "
                 "{%0,%1,%2,%3}, {%4,%5,%6,%7}, {%8,%9}, {%0,%1,%2,%3};"
                 : "+f"(c[0]), "+f"(c[1]), "+f"(c[2]), "+f"(c[3])
                 : "r"(a[0]), "r"(a[1]), "r"(a[2]), "r"(a[3]),
                   "r"(b[0]), "r"(b[1]));
}
__device__ __forceinline__ void mma_f8(float* c, const uint32_t* a, uint32_t b0, uint32_t b1) {
    asm volatile("mma.sync.aligned.m16n8k32.row.col.f32.e4m3.e4m3.f32 "
                 "{%0,%1,%2,%3}, {%4,%5,%6,%7}, {%8,%9}, {%0,%1,%2,%3};"
                 : "+f"(c[0]), "+f"(c[1]), "+f"(c[2]), "+f"(c[3])
                 : "r"(a[0]), "r"(a[1]), "r"(a[2]), "r"(a[3]),
                   "r"(b0), "r"(b1));
}
__device__ __forceinline__ void cpa16(uint32_t s, const void* g) {
    asm volatile("cp.async.cg.shared.global [%0], [%1], 16;" :: "r"(s), "l"(g));
}
__device__ __forceinline__ void cpa16p(uint32_t s, const void* g, int pred) {
    int sz = pred ? 16 : 0;
    asm volatile("cp.async.cg.shared.global [%0], [%1], 16, %2;" :: "r"(s), "l"(g), "r"(sz));
}
__device__ __forceinline__ uint32_t svta(const void* p) {
    return (uint32_t)__cvta_generic_to_shared(p);
}
__device__ __forceinline__ void ldsm4(uint32_t* r, uint32_t a) {
    asm volatile("ldmatrix.sync.aligned.m8n8.x4.shared.b16 {%0,%1,%2,%3}, [%4];"
                 : "=r"(r[0]), "=r"(r[1]), "=r"(r[2]), "=r"(r[3]) : "r"(a));
}
__device__ __forceinline__ void ldsm4t(uint32_t* r, uint32_t a) {
    asm volatile("ldmatrix.sync.aligned.m8n8.x4.trans.shared.b16 {%0,%1,%2,%3}, [%4];"
                 : "=r"(r[0]), "=r"(r[1]), "=r"(r[2]), "=r"(r[3]) : "r"(a));
}
__device__ __forceinline__ unsigned char f2e4m3(float x) {
    uint16_t r;
    asm("cvt.rn.satfinite.e4m3x2.f32 %0, %1, %2;" : "=h"(r) : "f"(0.0f), "f"(x));
    return (unsigned char)(r & 0xFF);
}

// ---------------- invalid-dtype detection + normalization --------------------
__global__ void k_detect_inv(const unsigned char* __restrict__ raw) {
    __shared__ int f_gt1, f_mod;
    if (threadIdx.x == 0) { f_gt1 = 0; f_mod = 0; }
    __syncthreads();
    const int NB = P * FH;
    int lg = 0, lm = 0;
    for (int i = threadIdx.x; i < NB; i += blockDim.x) {
        unsigned char v = raw[i];
        if (v > 1) lg = 1;
        if (v != 0 && (i & 3) != 0) lm = 1;
    }
    if (lg) atomicOr(&f_gt1, 1);
    if (lm) atomicOr(&f_mod, 1);
    __syncthreads();
    int mode = f_gt1 ? 2 : (f_mod ? 0 : 1);
    for (int i = threadIdx.x; i < NB; i += blockDim.x) {
        unsigned char o;
        if (mode == 0)      o = (raw[i] != 0);
        else if (mode == 1) o = (((const int*)raw)[i] != 0);
        else                o = (((const float*)raw)[i] != 0.0f);
        g_inv[i] = o;
    }
}

// ---------------- 1x1 conv ----------------
__global__ void k_conv(const float* __restrict__ x,
                       const float* __restrict__ w,
                       const float* __restrict__ bias) {
    __shared__ float xs[CIN];
    const int b = blockIdx.y, s = blockIdx.x;
    const int t = threadIdx.x;
    for (int c = t; c < CIN; c += 64)
        xs[c] = x[(size_t)(b*CIN + c)*HW + s];
    __syncthreads();
    float acc = bias[t];
    const float4* wp = (const float4*)(w + (size_t)t*CIN);
#pragma unroll 8
    for (int c4 = 0; c4 < CIN/4; c4++) {
        float4 wv = wp[c4];
        acc += xs[4*c4+0]*wv.x + xs[4*c4+1]*wv.y + xs[4*c4+2]*wv.z + xs[4*c4+3]*wv.w;
    }
    g_f[(size_t)(b*AFC + t)*HW + s] = acc;
}

// ---------------- att_w -> e4m3 (scaled x256) ----------------
__global__ void k_cvt_attw(const float* __restrict__ w) {
    int i = blockIdx.x*256 + threadIdx.x;
    if (i < PM1*DIM) g_attw8[i] = f2e4m3(w[i] * ATTW_SCALE);
}

// ---------------- gather (fp32 + bf16 + e4m3 outputs) ----------------
__global__ void k_gather(const int* __restrict__ cut_x) {
    const int row = blockIdx.x;
    const int b = row / P, p = row - b*P;
    __shared__ int cx[FH];
    __shared__ unsigned char iv[FH];
    if (threadIdx.x < FH) {
        cx[threadIdx.x] = cut_x[p*FH + threadIdx.x];
        iv[threadIdx.x] = g_inv[p*FH + threadIdx.x];
    }
    __syncthreads();
    for (int d = threadIdx.x; d < DIM; d += blockDim.x) {
        int c = d / FH, h = d - c*FH;
        float v = iv[h] ? 0.0f : g_f[(size_t)(b*AFC + c)*HW + h*FW + cx[h]];
        g_feat[(size_t)row*DIM + d]  = v;
        g_featb[(size_t)row*DIM + d] = __float2bfloat16(v);
        g_feat8[(size_t)row*DIM + d] = f2e4m3(v * FEAT_SCALE);
    }
}

// ============== GEMM1 (e4m3 mma k32 + ldmatrix, cp.async double-buffered) ====
// g_att[m][n] = (feat8[m][:].attw8[n][:]) / 16384 + bias[n]
// K = 704 elems = 11 chunks of 64 bytes
__global__ __launch_bounds__(256) void k_gemm1_f8(const float* __restrict__ bias) {
    __shared__ __align__(16) unsigned char As[2][128*AP8];
    __shared__ __align__(16) unsigned char Bs[2][128*AP8];
    const int bm = blockIdx.y*128, bn = blockIdx.x*128;
    const int tid = threadIdx.x, lane = tid & 31, wid = tid >> 5;
    const int wm = (wid >> 2)*64, wn = (wid & 3)*32;
    const int g = lane >> 2, t4 = lane & 3;
    float acc[4][4][4];
#pragma unroll
    for (int i = 0; i < 4; i++)
#pragma unroll
        for (int j = 0; j < 4; j++)
#pragma unroll
            for (int r = 0; r < 4; r++) acc[i][j][r] = 0.0f;

    // ldmatrix lane base offsets (bytes)
    const int a_off = (wm + (lane & 7) + 8*((lane >> 3) & 1))*AP8 + 16*(lane >> 4);
    const int b_off = (wn + (lane & 7) + 8*((lane >> 3) & 1))*AP8 + 16*(lane >> 4);
    const uint32_t AsB[2] = { svta(&As[0][0]), svta(&As[1][0]) };
    const uint32_t BsB[2] = { svta(&Bs[0][0]), svta(&Bs[1][0]) };

    auto stage = [&](int buf, int k0) {
#pragma unroll
        for (int q = 0; q < 2; q++) {
            int idx = tid + q*256;
            int r = idx >> 2, c16 = (idx & 3) << 4;   // 4 x 16B per 64B row
            cpa16(svta(&As[buf][r*AP8 + c16]),
                  g_feat8 + (size_t)(bm + r)*DIM + k0 + c16);
            int n = bn + r;
            int ok = (n < PM1);
            cpa16p(svta(&Bs[buf][r*AP8 + c16]),
                   g_attw8 + (size_t)(ok ? n : 0)*DIM + k0 + c16, ok);
        }
    };

    stage(0, 0);
    asm volatile("cp.async.commit_group;");
    int buf = 0;
    const int NK = DIM/64;   // 11
    for (int it = 0; it < NK; it++) {
        if (it + 1 < NK) {
            stage(buf ^ 1, (it + 1)*64);
            asm volatile("cp.async.commit_group;");
            asm volatile("cp.async.wait_group 1;");
        } else {
            asm volatile("cp.async.wait_group 0;");
        }
        __syncthreads();
#pragma unroll
        for (int ks = 0; ks < 2; ks++) {       // two k32 steps per 64B chunk
            uint32_t af[4][4], bq[2][4];
#pragma unroll
            for (int mt = 0; mt < 4; mt++)
                ldsm4(af[mt], AsB[buf] + a_off + mt*16*AP8 + ks*32);
#pragma unroll
            for (int ntp = 0; ntp < 2; ntp++)
                ldsm4(bq[ntp], BsB[buf] + b_off + ntp*16*AP8 + ks*32);
            // bq[ntp]: r0 = n(0-7) k0-15, r1 = n(8-15) k0-15, r2 = n(0-7) k16-31, r3 = n(8-15) k16-31
#pragma unroll
            for (int mt = 0; mt < 4; mt++)
#pragma unroll
                for (int nt = 0; nt < 4; nt++) {
                    int ntp = nt >> 1, sub = nt & 1;
                    mma_f8(acc[mt][nt], af[mt], bq[ntp][sub], bq[ntp][sub + 2]);
                }
        }
        __syncthreads();
        buf ^= 1;
    }
#pragma unroll
    for (int mt = 0; mt < 4; mt++) {
        int r0 = bm + wm + mt*16 + g;
#pragma unroll
        for (int nt = 0; nt < 4; nt++) {
            int n0 = bn + wn + nt*8 + t4*2;
            if (n0 < PM1)   g_att[(size_t)r0*PM1 + n0]       = acc[mt][nt][0]*SCORE_INV + bias[n0];
            if (n0+1 < PM1) g_att[(size_t)r0*PM1 + n0+1]     = acc[mt][nt][1]*SCORE_INV + bias[n0+1];
            if (n0 < PM1)   g_att[(size_t)(r0+8)*PM1 + n0]   = acc[mt][nt][2]*SCORE_INV + bias[n0];
            if (n0+1 < PM1) g_att[(size_t)(r0+8)*PM1 + n0+1] = acc[mt][nt][3]*SCORE_INV + bias[n0+1];
        }
    }
}

// ---------------- softmax: fp32 in, bf16 SHIFTED dense row out ---------------
__global__ void k_softmax() {
    __shared__ float srow[PM1];
    __shared__ float red[256];
    const size_t base  = (size_t)blockIdx.x * PM1;
    const size_t obase = (size_t)blockIdx.x * P;
    const int m = blockIdx.x % P;
    const int t = threadIdx.x;
    float mx = -1e30f;
    for (int i = t; i < PM1; i += 256) {
        float v = g_att[base + i]; srow[i] = v; mx = fmaxf(mx, v);
    }
    red[t] = mx; __syncthreads();
    for (int s = 128; s > 0; s >>= 1) { if (t < s) red[t] = fmaxf(red[t], red[t+s]); __syncthreads(); }
    mx = red[0]; __syncthreads();
    float sum = 0.0f;
    for (int i = t; i < PM1; i += 256) {
        float e = __expf(srow[i] - mx); srow[i] = e; sum += e;
    }
    red[t] = sum; __syncthreads();
    for (int s = 128; s > 0; s >>= 1) { if (t < s) red[t] += red[t+s]; __syncthreads(); }
    float inv = 1.0f / red[0];
    for (int i = t; i < PM1; i += 256)
        g_attsh[obase + i + (i >= m)] = __float2bfloat16(srow[i] * inv);
    if (t == 0) g_attsh[obase + m] = __float2bfloat16(0.0f);
}

// ============== GEMM2 (bf16 mma + ldmatrix[.trans], cp.async x2-buffered) ====
// att_feat[b] = A_shift[b] @ featb[b]; B staged raw (k-major), trans in LDSM.
__global__ __launch_bounds__(256) void k_gemm2_bf() {
    __shared__ __align__(16) __nv_bfloat16 As[2][128*AKH];
    __shared__ __align__(16) __nv_bfloat16 Bs[2][32*BNH];
    const int b  = blockIdx.z;
    const int m0 = blockIdx.y*128, n0 = blockIdx.x*128;
    const int tid = threadIdx.x, lane = tid & 31, wid = tid >> 5;
    const int wm = (wid >> 2)*64, wn = (wid & 3)*32;
    const int g = lane >> 2, t4 = lane & 3;
    const __nv_bfloat16* attsh = g_attsh + (size_t)b*P*P;
    const __nv_bfloat16* featb = g_featb + (size_t)b*P*DIM;
    float acc[4][4][4];
#pragma unroll
    for (int i = 0; i < 4; i++)
#pragma unroll
        for (int j = 0; j < 4; j++)
#pragma unroll
            for (int r = 0; r < 4; r++) acc[i][j][r] = 0.0f;

    const int a_off  = (wm + (lane & 7) + 8*((lane >> 3) & 1))*AKH + 8*(lane >> 4);
    const int bt_off = ((lane & 7) + 8*((lane >> 3) & 1))*BNH + wn + 8*(lane >> 4);
    const uint32_t AsB[2] = { svta(&As[0][0]), svta(&As[1][0]) };
    const uint32_t BsB[2] = { svta(&Bs[0][0]), svta(&Bs[1][0]) };

    auto stage = [&](int buf, int k0) {
#pragma unroll
        for (int q = 0; q < 2; q++) {
            int idx = tid + q*256;
            int r = idx >> 2, c8 = (idx & 3) << 3;
            int gm = m0 + r;
            int ok = (gm < P);
            cpa16p(svta(&As[buf][r*AKH + c8]),
                   attsh + (size_t)(ok ? gm : 0)*P + k0 + c8, ok);
        }
#pragma unroll
        for (int q = 0; q < 2; q++) {
            int idx = tid + q*256;
            int kr = idx >> 4, c8 = (idx & 15) << 3;
            int n = n0 + c8;
            int ok = (n < DIM);
            cpa16p(svta(&Bs[buf][kr*BNH + c8]),
                   featb + (size_t)(k0 + kr)*DIM + (ok ? n : 0), ok);
        }
    };

    stage(0, 0);
    asm volatile("cp.async.commit_group;");
    int buf = 0;
    const int NK = P/32;   // 87
    for (int it = 0; it < NK; it++) {
        if (it + 1 < NK) {
            stage(buf ^ 1, (it + 1)*32);
            asm volatile("cp.async.commit_group;");
            asm volatile("cp.async.wait_group 1;");
        } else {
            asm volatile("cp.async.wait_group 0;");
        }
        __syncthreads();
#pragma unroll
        for (int ks = 0; ks < 2; ks++) {
            const int kk = ks*16;
            uint32_t af[4][4], bq[2][4];
#pragma unroll
            for (int mt = 0; mt < 4; mt++)
                ldsm4(af[mt], AsB[buf] + 2*(a_off + mt*16*AKH + kk));
#pragma unroll
            for (int ntp = 0; ntp < 2; ntp++)
                ldsm4t(bq[ntp], BsB[buf] + 2*(bt_off + kk*BNH + ntp*16));
#pragma unroll
            for (int mt = 0; mt < 4; mt++)
#pragma unroll
                for (int nt = 0; nt < 4; nt++)
                    mma_bf16(acc[mt][nt], af[mt], &bq[nt >> 1][(nt & 1)*2]);
        }
        __syncthreads();
        buf ^= 1;
    }
#pragma unroll
    for (int mt = 0; mt < 4; mt++) {
        int r0 = m0 + wm + mt*16 + g;
#pragma unroll
        for (int nt = 0; nt < 4; nt++) {
            int n0c = n0 + wn + nt*8 + t4*2;
            if (r0 < P && n0c < DIM) {
                g_attfeat[(size_t)(b*P + r0)*DIM + n0c]   = acc[mt][nt][0];
                g_attfeat[(size_t)(b*P + r0)*DIM + n0c+1] = acc[mt][nt][1];
            }
            if (r0+8 < P && n0c < DIM) {
                g_attfeat[(size_t)(b*P + r0+8)*DIM + n0c]   = acc[mt][nt][2];
                g_attfeat[(size_t)(b*P + r0+8)*DIM + n0c+1] = acc[mt][nt][3];
            }
        }
    }
}

// ---------------- epilogue (fp32): [att_feat|feat] @ W^T + assembly ----------
#define SPAD 132
__global__ __launch_bounds__(256) void k_epi(const float* __restrict__ cls_w,
                                             const float* __restrict__ cls_b,
                                             const float* __restrict__ reg_w,
                                             const float* __restrict__ reg_b,
                                             const float* __restrict__ anchors,
                                             float* __restrict__ out) {
    __shared__ float As2[16][SPAD];
    __shared__ float Ws[16][80];
    const int m0 = blockIdx.x * 128;
    const int tid = threadIdx.x;
    const int ty = tid >> 4, tx = tid & 15;
    float acc[8][5];
#pragma unroll
    for (int i = 0; i < 8; i++)
#pragma unroll
        for (int j = 0; j < 5; j++) acc[i][j] = 0.0f;

    for (int k0 = 0; k0 < DIM2; k0 += 16) {
#pragma unroll
        for (int q = 0; q < 2; q++) {
            int idx = tid + q*256;
            int r = idx >> 2, c4 = (idx & 3) << 2;
            int gk = k0 + c4;
            const float* src = (gk < DIM)
                ? (g_attfeat + (size_t)(m0 + r)*DIM + gk)
                : (g_feat    + (size_t)(m0 + r)*DIM + (gk - DIM));
            float4 v = *(const float4*)src;
            As2[c4+0][r] = v.x; As2[c4+1][r] = v.y; As2[c4+2][r] = v.z; As2[c4+3][r] = v.w;
        }
        for (int i = tid; i < 16*80; i += 256) {
            int kk = i / 80, n = i - kk*80;
            int gk = k0 + kk;
            float v = 0.0f;
            if (n < 2)          v = cls_w[(size_t)n*DIM2 + gk];
            else if (n < NWOUT) v = reg_w[(size_t)(n-2)*DIM2 + gk];
            Ws[kk][n] = v;
        }
        __syncthreads();
#pragma unroll
        for (int kk = 0; kk < 16; kk++) {
            float a[8], w[5];
            *(float4*)(a)   = *(const float4*)&As2[kk][ty*8];
            *(float4*)(a+4) = *(const float4*)&As2[kk][ty*8+4];
#pragma unroll
            for (int j = 0; j < 5; j++) w[j] = Ws[kk][tx*5 + j];
#pragma unroll
            for (int i = 0; i < 8; i++)
#pragma unroll
                for (int j = 0; j < 5; j++) acc[i][j] += a[i]*w[j];
        }
        __syncthreads();
    }
    const size_t O0 = 0;
    const size_t O1 = (size_t)M_TOT * 72;
    const size_t O2 = O1 + M_TOT;
    const size_t O3 = O2 + M_TOT;
#pragma unroll
    for (int i = 0; i < 8; i++) {
        int row = m0 + ty*8 + i;
        int bidx = row / P, p = row - bidx*P;
        (void)bidx;
#pragma unroll
        for (int j = 0; j < 5; j++) {
            int n = tx*5 + j;
            if (n >= NWOUT) continue;
            float r = acc[i][j] + (n < 2 ? cls_b[n] : reg_b[n-2]);
            if (n < 2) {
                out[O3 + (size_t)row*2 + n] = r;
            } else if (n == 2) {
                out[O2 + row] = anchors[p*74 + 1] + r;
                out[O1 + row] = anchors[p*74 + 0];
            } else {
                out[O0 + (size_t)row*72 + (n-3)] = anchors[p*74 + 2 + (n-3)] + r;
            }
        }
    }
}

// ---------------- launch ----------------
extern "C" void kernel_launch(void* const* d_in, const int* in_sizes, int n_in,
                              void* d_out, int out_size) {
    const float* x       = (const float*)d_in[0];
    const float* conv_w  = (const float*)d_in[1];
    const float* conv_b  = (const float*)d_in[2];
    const float* att_w   = (const float*)d_in[3];
    const float* att_b   = (const float*)d_in[4];
    const float* cls_w   = (const float*)d_in[5];
    const float* cls_b   = (const float*)d_in[6];
    const float* reg_w   = (const float*)d_in[7];
    const float* reg_b   = (const float*)d_in[8];
    const float* anchors = (const float*)d_in[9];
    const int*   cut_x   = (const int*)d_in[10];
    const unsigned char* invalid = (const unsigned char*)d_in[11];
    float* out = (float*)d_out;
    (void)in_sizes; (void)n_in; (void)out_size;

    k_detect_inv<<<1, 1024>>>(invalid);
    k_conv<<<dim3(HW, BATCH), 64>>>(x, conv_w, conv_b);
    k_cvt_attw<<<(PM1*DIM + 255)/256, 256>>>(att_w);
    k_gather<<<M_TOT, 128>>>(cut_x);
    k_gemm1_f8<<<dim3((PM1 + 127)/128, M_TOT/128), 256>>>(att_b);
    k_softmax<<<M_TOT, 256>>>();
    k_gemm2_bf<<<dim3((DIM + 127)/128, (P + 127)/128, BATCH), 256>>>();
    k_epi<<<M_TOT/128, 256>>>(cls_w, cls_b, reg_w, reg_b, anchors, out);
}

// round 10
// speedup vs baseline: 4.4846x; 1.0295x over previous
#include <cuda_runtime.h>
#include <cuda_bf16.h>
#include <cstdint>
#include <cstddef>

// ---------------- problem constants ----------------
#define BATCH   8
#define P       2784
#define PM1     2783
#define FH      11
#define FW      20
#define HW      220
#define CIN     512
#define AFC     64
#define DIM     704
#define DIM2    1408
#define NWOUT   75
#define M_TOT   (BATCH*P)   // 22272 = 174*128
#define AKH     40          // bf16 k-major smem pitch in halfs (32 data + 8 pad)
#define BNH     136         // gemm2 B (n-major) smem pitch in halfs (128 + 8 pad)
#define AP8     80          // fp8 smem pitch in bytes (64 data + 16 pad)
#define FEAT_SCALE 64.0f
#define ATTW_SCALE 256.0f
#define SCORE_INV  (1.0f/16384.0f)

// ---------------- scratch ----------------
__device__ float          g_f[BATCH*AFC*HW];
__device__ float          g_feat[(size_t)M_TOT*DIM];          // fp32 feat (epi)
__device__ __nv_bfloat16  g_featb[(size_t)M_TOT*DIM];         // bf16 feat (gemm2)
__device__ unsigned char  g_feat8[(size_t)M_TOT*DIM];         // e4m3 feat*64 (gemm1)
__device__ unsigned char  g_attw8[(size_t)PM1*DIM];           // e4m3 att_w*256 (gemm1)
__device__ __nv_bfloat16  g_attb16[(size_t)M_TOT*PM1];        // bf16 scores
__device__ __nv_bfloat16  g_attsh[(size_t)M_TOT*P];           // bf16 SHIFTED softmax (dense PxP)
__device__ float          g_attfeat[(size_t)M_TOT*DIM];       // fp32 attention output (epi)
__device__ unsigned char  g_inv[P*FH];

// ---------------- helpers ----------------
__device__ __forceinline__ void mma_bf16(float* c, const uint32_t* a, const uint32_t* b) {
    asm volatile("mma.sync.aligned.m16n8k16.row.col.f32.bf16.bf16.f32 "
                 "{%0,%1,%2,%3}, {%4,%5,%6,%7}, {%8,%9}, {%0,%1,%2,%3};"
                 : "+f"(c[0]), "+f"(c[1]), "+f"(c[2]), "+f"(c[3])
                 : "r"(a[0]), "r"(a[1]), "r"(a[2]), "r"(a[3]),
                   "r"(b[0]), "r"(b[1]));
}
__device__ __forceinline__ void mma_f8(float* c, const uint32_t* a, uint32_t b0, uint32_t b1) {
    asm volatile("mma.sync.aligned.m16n8k32.row.col.f32.e4m3.e4m3.f32 "
                 "{%0,%1,%2,%3}, {%4,%5,%6,%7}, {%8,%9}, {%0,%1,%2,%3};"
                 : "+f"(c[0]), "+f"(c[1]), "+f"(c[2]), "+f"(c[3])
                 : "r"(a[0]), "r"(a[1]), "r"(a[2]), "r"(a[3]),
                   "r"(b0), "r"(b1));
}
__device__ __forceinline__ void cpa16(uint32_t s, const void* g) {
    asm volatile("cp.async.cg.shared.global [%0], [%1], 16;" :: "r"(s), "l"(g));
}
__device__ __forceinline__ void cpa16p(uint32_t s, const void* g, int pred) {
    int sz = pred ? 16 : 0;
    asm volatile("cp.async.cg.shared.global [%0], [%1], 16, %2;" :: "r"(s), "l"(g), "r"(sz));
}
__device__ __forceinline__ uint32_t svta(const void* p) {
    return (uint32_t)__cvta_generic_to_shared(p);
}
__device__ __forceinline__ void ldsm4(uint32_t* r, uint32_t a) {
    asm volatile("ldmatrix.sync.aligned.m8n8.x4.shared.b16 {%0,%1,%2,%3}, [%4];"
                 : "=r"(r[0]), "=r"(r[1]), "=r"(r[2]), "=r"(r[3]) : "r"(a));
}
__device__ __forceinline__ void ldsm4t(uint32_t* r, uint32_t a) {
    asm volatile("ldmatrix.sync.aligned.m8n8.x4.trans.shared.b16 {%0,%1,%2,%3}, [%4];"
                 : "=r"(r[0]), "=r"(r[1]), "=r"(r[2]), "=r"(r[3]) : "r"(a));
}
__device__ __forceinline__ unsigned char f2e4m3(float x) {
    uint16_t r;
    asm("cvt.rn.satfinite.e4m3x2.f32 %0, %1, %2;" : "=h"(r) : "f"(0.0f), "f"(x));
    return (unsigned char)(r & 0xFF);
}

// ---------------- invalid-dtype detection + normalization --------------------
__global__ void k_detect_inv(const unsigned char* __restrict__ raw) {
    __shared__ int f_gt1, f_mod;
    if (threadIdx.x == 0) { f_gt1 = 0; f_mod = 0; }
    __syncthreads();
    const int NB = P * FH;
    int lg = 0, lm = 0;
    for (int i = threadIdx.x; i < NB; i += blockDim.x) {
        unsigned char v = raw[i];
        if (v > 1) lg = 1;
        if (v != 0 && (i & 3) != 0) lm = 1;
    }
    if (lg) atomicOr(&f_gt1, 1);
    if (lm) atomicOr(&f_mod, 1);
    __syncthreads();
    int mode = f_gt1 ? 2 : (f_mod ? 0 : 1);
    for (int i = threadIdx.x; i < NB; i += blockDim.x) {
        unsigned char o;
        if (mode == 0)      o = (raw[i] != 0);
        else if (mode == 1) o = (((const int*)raw)[i] != 0);
        else                o = (((const float*)raw)[i] != 0.0f);
        g_inv[i] = o;
    }
}

// ---------------- 1x1 conv ----------------
__global__ void k_conv(const float* __restrict__ x,
                       const float* __restrict__ w,
                       const float* __restrict__ bias) {
    __shared__ float xs[CIN];
    const int b = blockIdx.y, s = blockIdx.x;
    const int t = threadIdx.x;
    for (int c = t; c < CIN; c += 64)
        xs[c] = x[(size_t)(b*CIN + c)*HW + s];
    __syncthreads();
    float acc = bias[t];
    const float4* wp = (const float4*)(w + (size_t)t*CIN);
#pragma unroll 8
    for (int c4 = 0; c4 < CIN/4; c4++) {
        float4 wv = wp[c4];
        acc += xs[4*c4+0]*wv.x + xs[4*c4+1]*wv.y + xs[4*c4+2]*wv.z + xs[4*c4+3]*wv.w;
    }
    g_f[(size_t)(b*AFC + t)*HW + s] = acc;
}

// ---------------- att_w -> e4m3 (scaled x256) ----------------
__global__ void k_cvt_attw(const float* __restrict__ w) {
    int i = blockIdx.x*256 + threadIdx.x;
    if (i < PM1*DIM) g_attw8[i] = f2e4m3(w[i] * ATTW_SCALE);
}

// ---------------- gather (fp32 + bf16 + e4m3 outputs) ----------------
__global__ void k_gather(const int* __restrict__ cut_x) {
    const int row = blockIdx.x;
    const int b = row / P, p = row - b*P;
    __shared__ int cx[FH];
    __shared__ unsigned char iv[FH];
    if (threadIdx.x < FH) {
        cx[threadIdx.x] = cut_x[p*FH + threadIdx.x];
        iv[threadIdx.x] = g_inv[p*FH + threadIdx.x];
    }
    __syncthreads();
    for (int d = threadIdx.x; d < DIM; d += blockDim.x) {
        int c = d / FH, h = d - c*FH;
        float v = iv[h] ? 0.0f : g_f[(size_t)(b*AFC + c)*HW + h*FW + cx[h]];
        g_feat[(size_t)row*DIM + d]  = v;
        g_featb[(size_t)row*DIM + d] = __float2bfloat16(v);
        g_feat8[(size_t)row*DIM + d] = f2e4m3(v * FEAT_SCALE);
    }
}

// ============== GEMM1 (e4m3 mma k32 + ldmatrix, cp.async double-buffered) ====
// g_attb16[m][n] = bf16( feat8[m][:].attw8[n][:] / 16384 + bias[n] )
__global__ __launch_bounds__(256) void k_gemm1_f8(const float* __restrict__ bias) {
    __shared__ __align__(16) unsigned char As[2][128*AP8];
    __shared__ __align__(16) unsigned char Bs[2][128*AP8];
    const int bm = blockIdx.y*128, bn = blockIdx.x*128;
    const int tid = threadIdx.x, lane = tid & 31, wid = tid >> 5;
    const int wm = (wid >> 2)*64, wn = (wid & 3)*32;
    const int g = lane >> 2, t4 = lane & 3;
    float acc[4][4][4];
#pragma unroll
    for (int i = 0; i < 4; i++)
#pragma unroll
        for (int j = 0; j < 4; j++)
#pragma unroll
            for (int r = 0; r < 4; r++) acc[i][j][r] = 0.0f;

    const int a_off = (wm + (lane & 7) + 8*((lane >> 3) & 1))*AP8 + 16*(lane >> 4);
    const int b_off = (wn + (lane & 7) + 8*((lane >> 3) & 1))*AP8 + 16*(lane >> 4);
    const uint32_t AsB[2] = { svta(&As[0][0]), svta(&As[1][0]) };
    const uint32_t BsB[2] = { svta(&Bs[0][0]), svta(&Bs[1][0]) };

    auto stage = [&](int buf, int k0) {
#pragma unroll
        for (int q = 0; q < 2; q++) {
            int idx = tid + q*256;
            int r = idx >> 2, c16 = (idx & 3) << 4;
            cpa16(svta(&As[buf][r*AP8 + c16]),
                  g_feat8 + (size_t)(bm + r)*DIM + k0 + c16);
            int n = bn + r;
            int ok = (n < PM1);
            cpa16p(svta(&Bs[buf][r*AP8 + c16]),
                   g_attw8 + (size_t)(ok ? n : 0)*DIM + k0 + c16, ok);
        }
    };

    stage(0, 0);
    asm volatile("cp.async.commit_group;");
    int buf = 0;
    const int NK = DIM/64;   // 11
    for (int it = 0; it < NK; it++) {
        if (it + 1 < NK) {
            stage(buf ^ 1, (it + 1)*64);
            asm volatile("cp.async.commit_group;");
            asm volatile("cp.async.wait_group 1;");
        } else {
            asm volatile("cp.async.wait_group 0;");
        }
        __syncthreads();
#pragma unroll
        for (int ks = 0; ks < 2; ks++) {
            uint32_t af[4][4], bq[2][4];
#pragma unroll
            for (int mt = 0; mt < 4; mt++)
                ldsm4(af[mt], AsB[buf] + a_off + mt*16*AP8 + ks*32);
#pragma unroll
            for (int ntp = 0; ntp < 2; ntp++)
                ldsm4(bq[ntp], BsB[buf] + b_off + ntp*16*AP8 + ks*32);
#pragma unroll
            for (int mt = 0; mt < 4; mt++)
#pragma unroll
                for (int nt = 0; nt < 4; nt++) {
                    int ntp = nt >> 1, sub = nt & 1;
                    mma_f8(acc[mt][nt], af[mt], bq[ntp][sub], bq[ntp][sub + 2]);
                }
        }
        __syncthreads();
        buf ^= 1;
    }
#pragma unroll
    for (int mt = 0; mt < 4; mt++) {
        int r0 = bm + wm + mt*16 + g;
#pragma unroll
        for (int nt = 0; nt < 4; nt++) {
            int n0 = bn + wn + nt*8 + t4*2;
            if (n0 < PM1)
                g_attb16[(size_t)r0*PM1 + n0]       = __float2bfloat16(acc[mt][nt][0]*SCORE_INV + bias[n0]);
            if (n0+1 < PM1)
                g_attb16[(size_t)r0*PM1 + n0+1]     = __float2bfloat16(acc[mt][nt][1]*SCORE_INV + bias[n0+1]);
            if (n0 < PM1)
                g_attb16[(size_t)(r0+8)*PM1 + n0]   = __float2bfloat16(acc[mt][nt][2]*SCORE_INV + bias[n0]);
            if (n0+1 < PM1)
                g_attb16[(size_t)(r0+8)*PM1 + n0+1] = __float2bfloat16(acc[mt][nt][3]*SCORE_INV + bias[n0+1]);
        }
    }
}

// ---------------- softmax: bf16 in, bf16 SHIFTED dense row out ---------------
// row cached in registers (11 per thread), smem only for cross-warp reduce
#define SITER ((PM1 + 255)/256)   // 11
__global__ __launch_bounds__(256) void k_softmax() {
    __shared__ float red[256];
    const size_t base  = (size_t)blockIdx.x * PM1;
    const size_t obase = (size_t)blockIdx.x * P;
    const int m = blockIdx.x % P;
    const int t = threadIdx.x;
    float vals[SITER];
    float mx = -1e30f;
#pragma unroll
    for (int j = 0; j < SITER; j++) {
        int i = t + j*256;
        float v = (i < PM1) ? __bfloat162float(g_attb16[base + i]) : -1e30f;
        vals[j] = v; mx = fmaxf(mx, v);
    }
    red[t] = mx; __syncthreads();
    for (int s = 128; s > 0; s >>= 1) { if (t < s) red[t] = fmaxf(red[t], red[t+s]); __syncthreads(); }
    mx = red[0]; __syncthreads();
    float sum = 0.0f;
#pragma unroll
    for (int j = 0; j < SITER; j++) {
        int i = t + j*256;
        float e = (i < PM1) ? __expf(vals[j] - mx) : 0.0f;
        vals[j] = e; sum += e;
    }
    red[t] = sum; __syncthreads();
    for (int s = 128; s > 0; s >>= 1) { if (t < s) red[t] += red[t+s]; __syncthreads(); }
    float inv = 1.0f / red[0];
#pragma unroll
    for (int j = 0; j < SITER; j++) {
        int i = t + j*256;
        if (i < PM1)
            g_attsh[obase + i + (i >= m)] = __float2bfloat16(vals[j] * inv);
    }
    if (t == 0) g_attsh[obase + m] = __float2bfloat16(0.0f);
}

// ============== GEMM2 (bf16 mma + ldmatrix[.trans], cp.async x2-buffered) ====
// att_feat[b] = A_shift[b] @ featb[b]; fp32 output for epilogue precision.
__global__ __launch_bounds__(256) void k_gemm2_bf() {
    __shared__ __align__(16) __nv_bfloat16 As[2][128*AKH];
    __shared__ __align__(16) __nv_bfloat16 Bs[2][32*BNH];
    const int b  = blockIdx.z;
    const int m0 = blockIdx.y*128, n0 = blockIdx.x*128;
    const int tid = threadIdx.x, lane = tid & 31, wid = tid >> 5;
    const int wm = (wid >> 2)*64, wn = (wid & 3)*32;
    const int g = lane >> 2, t4 = lane & 3;
    const __nv_bfloat16* attsh = g_attsh + (size_t)b*P*P;
    const __nv_bfloat16* featb = g_featb + (size_t)b*P*DIM;
    float acc[4][4][4];
#pragma unroll
    for (int i = 0; i < 4; i++)
#pragma unroll
        for (int j = 0; j < 4; j++)
#pragma unroll
            for (int r = 0; r < 4; r++) acc[i][j][r] = 0.0f;

    const int a_off  = (wm + (lane & 7) + 8*((lane >> 3) & 1))*AKH + 8*(lane >> 4);
    const int bt_off = ((lane & 7) + 8*((lane >> 3) & 1))*BNH + wn + 8*(lane >> 4);
    const uint32_t AsB[2] = { svta(&As[0][0]), svta(&As[1][0]) };
    const uint32_t BsB[2] = { svta(&Bs[0][0]), svta(&Bs[1][0]) };

    auto stage = [&](int buf, int k0) {
#pragma unroll
        for (int q = 0; q < 2; q++) {
            int idx = tid + q*256;
            int r = idx >> 2, c8 = (idx & 3) << 3;
            int gm = m0 + r;
            int ok = (gm < P);
            cpa16p(svta(&As[buf][r*AKH + c8]),
                   attsh + (size_t)(ok ? gm : 0)*P + k0 + c8, ok);
        }
#pragma unroll
        for (int q = 0; q < 2; q++) {
            int idx = tid + q*256;
            int kr = idx >> 4, c8 = (idx & 15) << 3;
            int n = n0 + c8;
            int ok = (n < DIM);
            cpa16p(svta(&Bs[buf][kr*BNH + c8]),
                   featb + (size_t)(k0 + kr)*DIM + (ok ? n : 0), ok);
        }
    };

    stage(0, 0);
    asm volatile("cp.async.commit_group;");
    int buf = 0;
    const int NK = P/32;   // 87
    for (int it = 0; it < NK; it++) {
        if (it + 1 < NK) {
            stage(buf ^ 1, (it + 1)*32);
            asm volatile("cp.async.commit_group;");
            asm volatile("cp.async.wait_group 1;");
        } else {
            asm volatile("cp.async.wait_group 0;");
        }
        __syncthreads();
#pragma unroll
        for (int ks = 0; ks < 2; ks++) {
            const int kk = ks*16;
            uint32_t af[4][4], bq[2][4];
#pragma unroll
            for (int mt = 0; mt < 4; mt++)
                ldsm4(af[mt], AsB[buf] + 2*(a_off + mt*16*AKH + kk));
#pragma unroll
            for (int ntp = 0; ntp < 2; ntp++)
                ldsm4t(bq[ntp], BsB[buf] + 2*(bt_off + kk*BNH + ntp*16));
#pragma unroll
            for (int mt = 0; mt < 4; mt++)
#pragma unroll
                for (int nt = 0; nt < 4; nt++)
                    mma_bf16(acc[mt][nt], af[mt], &bq[nt >> 1][(nt & 1)*2]);
        }
        __syncthreads();
        buf ^= 1;
    }
#pragma unroll
    for (int mt = 0; mt < 4; mt++) {
        int r0 = m0 + wm + mt*16 + g;
#pragma unroll
        for (int nt = 0; nt < 4; nt++) {
            int n0c = n0 + wn + nt*8 + t4*2;
            if (r0 < P && n0c < DIM) {
                g_attfeat[(size_t)(b*P + r0)*DIM + n0c]   = acc[mt][nt][0];
                g_attfeat[(size_t)(b*P + r0)*DIM + n0c+1] = acc[mt][nt][1];
            }
            if (r0+8 < P && n0c < DIM) {
                g_attfeat[(size_t)(b*P + r0+8)*DIM + n0c]   = acc[mt][nt][2];
                g_attfeat[(size_t)(b*P + r0+8)*DIM + n0c+1] = acc[mt][nt][3];
            }
        }
    }
}

// ---------------- epilogue (fp32): [att_feat|feat] @ W^T + assembly ----------
#define SPAD 132
__global__ __launch_bounds__(256) void k_epi(const float* __restrict__ cls_w,
                                             const float* __restrict__ cls_b,
                                             const float* __restrict__ reg_w,
                                             const float* __restrict__ reg_b,
                                             const float* __restrict__ anchors,
                                             float* __restrict__ out) {
    __shared__ float As2[16][SPAD];
    __shared__ float Ws[16][80];
    const int m0 = blockIdx.x * 128;
    const int tid = threadIdx.x;
    const int ty = tid >> 4, tx = tid & 15;
    float acc[8][5];
#pragma unroll
    for (int i = 0; i < 8; i++)
#pragma unroll
        for (int j = 0; j < 5; j++) acc[i][j] = 0.0f;

    for (int k0 = 0; k0 < DIM2; k0 += 16) {
#pragma unroll
        for (int q = 0; q < 2; q++) {
            int idx = tid + q*256;
            int r = idx >> 2, c4 = (idx & 3) << 2;
            int gk = k0 + c4;
            const float* src = (gk < DIM)
                ? (g_attfeat + (size_t)(m0 + r)*DIM + gk)
                : (g_feat    + (size_t)(m0 + r)*DIM + (gk - DIM));
            float4 v = *(const float4*)src;
            As2[c4+0][r] = v.x; As2[c4+1][r] = v.y; As2[c4+2][r] = v.z; As2[c4+3][r] = v.w;
        }
        for (int i = tid; i < 16*80; i += 256) {
            int kk = i / 80, n = i - kk*80;
            int gk = k0 + kk;
            float v = 0.0f;
            if (n < 2)          v = cls_w[(size_t)n*DIM2 + gk];
            else if (n < NWOUT) v = reg_w[(size_t)(n-2)*DIM2 + gk];
            Ws[kk][n] = v;
        }
        __syncthreads();
#pragma unroll
        for (int kk = 0; kk < 16; kk++) {
            float a[8], w[5];
            *(float4*)(a)   = *(const float4*)&As2[kk][ty*8];
            *(float4*)(a+4) = *(const float4*)&As2[kk][ty*8+4];
#pragma unroll
            for (int j = 0; j < 5; j++) w[j] = Ws[kk][tx*5 + j];
#pragma unroll
            for (int i = 0; i < 8; i++)
#pragma unroll
                for (int j = 0; j < 5; j++) acc[i][j] += a[i]*w[j];
        }
        __syncthreads();
    }
    const size_t O0 = 0;
    const size_t O1 = (size_t)M_TOT * 72;
    const size_t O2 = O1 + M_TOT;
    const size_t O3 = O2 + M_TOT;
#pragma unroll
    for (int i = 0; i < 8; i++) {
        int row = m0 + ty*8 + i;
        int bidx = row / P, p = row - bidx*P;
        (void)bidx;
#pragma unroll
        for (int j = 0; j < 5; j++) {
            int n = tx*5 + j;
            if (n >= NWOUT) continue;
            float r = acc[i][j] + (n < 2 ? cls_b[n] : reg_b[n-2]);
            if (n < 2) {
                out[O3 + (size_t)row*2 + n] = r;
            } else if (n == 2) {
                out[O2 + row] = anchors[p*74 + 1] + r;
                out[O1 + row] = anchors[p*74 + 0];
            } else {
                out[O0 + (size_t)row*72 + (n-3)] = anchors[p*74 + 2 + (n-3)] + r;
            }
        }
    }
}

// ---------------- launch ----------------
extern "C" void kernel_launch(void* const* d_in, const int* in_sizes, int n_in,
                              void* d_out, int out_size) {
    const float* x       = (const float*)d_in[0];
    const float* conv_w  = (const float*)d_in[1];
    const float* conv_b  = (const float*)d_in[2];
    const float* att_w   = (const float*)d_in[3];
    const float* att_b   = (const float*)d_in[4];
    const float* cls_w   = (const float*)d_in[5];
    const float* cls_b   = (const float*)d_in[6];
    const float* reg_w   = (const float*)d_in[7];
    const float* reg_b   = (const float*)d_in[8];
    const float* anchors = (const float*)d_in[9];
    const int*   cut_x   = (const int*)d_in[10];
    const unsigned char* invalid = (const unsigned char*)d_in[11];
    float* out = (float*)d_out;
    (void)in_sizes; (void)n_in; (void)out_size;

    k_detect_inv<<<1, 1024>>>(invalid);
    k_conv<<<dim3(HW, BATCH), 64>>>(x, conv_w, conv_b);
    k_cvt_attw<<<(PM1*DIM + 255)/256, 256>>>(att_w);
    k_gather<<<M_TOT, 128>>>(cut_x);
    k_gemm1_f8<<<dim3((PM1 + 127)/128, M_TOT/128), 256>>>(att_b);
    k_softmax<<<M_TOT, 256>>>();
    k_gemm2_bf<<<dim3((DIM + 127)/128, (P + 127)/128, BATCH), 256>>>();
    k_epi<<<M_TOT/128, 256>>>(cls_w, cls_b, reg_w, reg_b, anchors, out);
}

// round 11
// speedup vs baseline: 5.5187x; 1.2306x over previous
#include <cuda_runtime.h>
#include <cuda_bf16.h>
#include <cstdint>
#include <cstddef>

// ---------------- problem constants ----------------
#define BATCH   8
#define P       2784
#define PM1     2783
#define FH      11
#define FW      20
#define HW      220
#define CIN     512
#define AFC     64
#define DIM     704
#define DIM2    1408
#define NWOUT   75
#define M_TOT   (BATCH*P)   // 22272 = 174*128
#define AKH     40          // bf16 k-major smem pitch in halfs (32 data + 8 pad)
#define BNH     136         // gemm3 B (n-major) smem pitch in halfs (128 + 8 pad)
#define AP8     80          // fp8 smem pitch in bytes (64 data + 16 pad)
#define RP      128         // R row pitch (bf16), cols 75..127 zero
#define FP      80          // F row pitch (fp32)
#define FEAT_SCALE 64.0f
#define ATTW_SCALE 256.0f
#define SCORE_INV  (1.0f/16384.0f)

// ---------------- scratch ----------------
__device__ float          g_f[BATCH*AFC*HW];
__device__ float          g_feat[(size_t)M_TOT*DIM];          // fp32 feat (k_head)
__device__ unsigned char  g_feat8[(size_t)M_TOT*DIM];         // e4m3 feat*64 (gemm1)
__device__ unsigned char  g_attw8[(size_t)PM1*DIM];           // e4m3 att_w*256 (gemm1)
__device__ __nv_bfloat16  g_attb16[(size_t)M_TOT*PM1];        // bf16 scores
__device__ __nv_bfloat16  g_attsh[(size_t)M_TOT*P];           // bf16 SHIFTED softmax (dense PxP)
__device__ __nv_bfloat16  g_Rb[(size_t)M_TOT*RP];             // bf16 R = feat @ Wa^T (padded)
__device__ float          g_F[(size_t)M_TOT*FP];              // fp32 F = feat @ Wf^T
__device__ unsigned char  g_inv[P*FH];

// ---------------- helpers ----------------
__device__ __forceinline__ void mma_bf16(float* c, const uint32_t* a, const uint32_t* b) {
    asm volatile("mma.sync.aligned.m16n8k16.row.col.f32.bf16.bf16.f32 "
                 "{%0,%1,%2,%3}, {%4,%5,%6,%7}, {%8,%9}, {%0,%1,%2,%3};"
                 : "+f"(c[0]), "+f"(c[1]), "+f"(c[2]), "+f"(c[3])
                 : "r"(a[0]), "r"(a[1]), "r"(a[2]), "r"(a[3]),
                   "r"(b[0]), "r"(b[1]));
}
__device__ __forceinline__ void mma_f8(float* c, const uint32_t* a, uint32_t b0, uint32_t b1) {
    asm volatile("mma.sync.aligned.m16n8k32.row.col.f32.e4m3.e4m3.f32 "
                 "{%0,%1,%2,%3}, {%4,%5,%6,%7}, {%8,%9}, {%0,%1,%2,%3};"
                 : "+f"(c[0]), "+f"(c[1]), "+f"(c[2]), "+f"(c[3])
                 : "r"(a[0]), "r"(a[1]), "r"(a[2]), "r"(a[3]),
                   "r"(b0), "r"(b1));
}
__device__ __forceinline__ void cpa16(uint32_t s, const void* g) {
    asm volatile("cp.async.cg.shared.global [%0], [%1], 16;" :: "r"(s), "l"(g));
}
__device__ __forceinline__ void cpa16p(uint32_t s, const void* g, int pred) {
    int sz = pred ? 16 : 0;
    asm volatile("cp.async.cg.shared.global [%0], [%1], 16, %2;" :: "r"(s), "l"(g), "r"(sz));
}
__device__ __forceinline__ uint32_t svta(const void* p) {
    return (uint32_t)__cvta_generic_to_shared(p);
}
__device__ __forceinline__ void ldsm4(uint32_t* r, uint32_t a) {
    asm volatile("ldmatrix.sync.aligned.m8n8.x4.shared.b16 {%0,%1,%2,%3}, [%4];"
                 : "=r"(r[0]), "=r"(r[1]), "=r"(r[2]), "=r"(r[3]) : "r"(a));
}
__device__ __forceinline__ void ldsm4t(uint32_t* r, uint32_t a) {
    asm volatile("ldmatrix.sync.aligned.m8n8.x4.trans.shared.b16 {%0,%1,%2,%3}, [%4];"
                 : "=r"(r[0]), "=r"(r[1]), "=r"(r[2]), "=r"(r[3]) : "r"(a));
}
__device__ __forceinline__ unsigned char f2e4m3(float x) {
    uint16_t r;
    asm("cvt.rn.satfinite.e4m3x2.f32 %0, %1, %2;" : "=h"(r) : "f"(0.0f), "f"(x));
    return (unsigned char)(r & 0xFF);
}

// ---------------- invalid-dtype detection + normalization --------------------
__global__ void k_detect_inv(const unsigned char* __restrict__ raw) {
    __shared__ int f_gt1, f_mod;
    if (threadIdx.x == 0) { f_gt1 = 0; f_mod = 0; }
    __syncthreads();
    const int NB = P * FH;
    int lg = 0, lm = 0;
    for (int i = threadIdx.x; i < NB; i += blockDim.x) {
        unsigned char v = raw[i];
        if (v > 1) lg = 1;
        if (v != 0 && (i & 3) != 0) lm = 1;
    }
    if (lg) atomicOr(&f_gt1, 1);
    if (lm) atomicOr(&f_mod, 1);
    __syncthreads();
    int mode = f_gt1 ? 2 : (f_mod ? 0 : 1);
    for (int i = threadIdx.x; i < NB; i += blockDim.x) {
        unsigned char o;
        if (mode == 0)      o = (raw[i] != 0);
        else if (mode == 1) o = (((const int*)raw)[i] != 0);
        else                o = (((const float*)raw)[i] != 0.0f);
        g_inv[i] = o;
    }
}

// ---------------- 1x1 conv ----------------
__global__ void k_conv(const float* __restrict__ x,
                       const float* __restrict__ w,
                       const float* __restrict__ bias) {
    __shared__ float xs[CIN];
    const int b = blockIdx.y, s = blockIdx.x;
    const int t = threadIdx.x;
    for (int c = t; c < CIN; c += 64)
        xs[c] = x[(size_t)(b*CIN + c)*HW + s];
    __syncthreads();
    float acc = bias[t];
    const float4* wp = (const float4*)(w + (size_t)t*CIN);
#pragma unroll 8
    for (int c4 = 0; c4 < CIN/4; c4++) {
        float4 wv = wp[c4];
        acc += xs[4*c4+0]*wv.x + xs[4*c4+1]*wv.y + xs[4*c4+2]*wv.z + xs[4*c4+3]*wv.w;
    }
    g_f[(size_t)(b*AFC + t)*HW + s] = acc;
}

// ---------------- att_w -> e4m3 (scaled x256) ----------------
__global__ void k_cvt_attw(const float* __restrict__ w) {
    int i = blockIdx.x*256 + threadIdx.x;
    if (i < PM1*DIM) g_attw8[i] = f2e4m3(w[i] * ATTW_SCALE);
}

// ---------------- gather (fp32 + e4m3 outputs) ----------------
__global__ void k_gather(const int* __restrict__ cut_x) {
    const int row = blockIdx.x;
    const int b = row / P, p = row - b*P;
    __shared__ int cx[FH];
    __shared__ unsigned char iv[FH];
    if (threadIdx.x < FH) {
        cx[threadIdx.x] = cut_x[p*FH + threadIdx.x];
        iv[threadIdx.x] = g_inv[p*FH + threadIdx.x];
    }
    __syncthreads();
    for (int d = threadIdx.x; d < DIM; d += blockDim.x) {
        int c = d / FH, h = d - c*FH;
        float v = iv[h] ? 0.0f : g_f[(size_t)(b*AFC + c)*HW + h*FW + cx[h]];
        g_feat[(size_t)row*DIM + d]  = v;
        g_feat8[(size_t)row*DIM + d] = f2e4m3(v * FEAT_SCALE);
    }
}

// ============== k_head: R = feat @ Wa^T (bf16 out), F = feat @ Wf^T (fp32) ===
// Wa[n] = W[n][0:704], Wf[n] = W[n][704:1408], W = [cls_w; reg_w] rows (75).
#define SPAD 132
#define NH 160
__global__ __launch_bounds__(256) void k_head(const float* __restrict__ cls_w,
                                              const float* __restrict__ reg_w) {
    __shared__ float As2[16][SPAD];
    __shared__ float Ws[16][NH];
    const int m0 = blockIdx.x * 128;
    const int tid = threadIdx.x;
    const int ty = tid >> 4, tx = tid & 15;
    float acc[8][10];
#pragma unroll
    for (int i = 0; i < 8; i++)
#pragma unroll
        for (int j = 0; j < 10; j++) acc[i][j] = 0.0f;

    for (int k0 = 0; k0 < DIM; k0 += 16) {
#pragma unroll
        for (int q = 0; q < 2; q++) {
            int idx = tid + q*256;
            int r = idx >> 2, c4 = (idx & 3) << 2;
            float4 v = *(const float4*)(g_feat + (size_t)(m0 + r)*DIM + k0 + c4);
            As2[c4+0][r] = v.x; As2[c4+1][r] = v.y; As2[c4+2][r] = v.z; As2[c4+3][r] = v.w;
        }
        for (int i = tid; i < 16*NH; i += 256) {
            int kk = i / NH, n = i - kk*NH;
            int half = (n >= 80) ? 1 : 0;
            int nn = n - 80*half;
            int col = k0 + kk + 704*half;
            float v = 0.0f;
            if (nn < 2)          v = cls_w[(size_t)nn*DIM2 + col];
            else if (nn < NWOUT) v = reg_w[(size_t)(nn-2)*DIM2 + col];
            Ws[kk][n] = v;
        }
        __syncthreads();
#pragma unroll
        for (int kk = 0; kk < 16; kk++) {
            float a[8], w[10];
            *(float4*)(a)   = *(const float4*)&As2[kk][ty*8];
            *(float4*)(a+4) = *(const float4*)&As2[kk][ty*8+4];
#pragma unroll
            for (int j = 0; j < 10; j++) w[j] = Ws[kk][tx*10 + j];
#pragma unroll
            for (int i = 0; i < 8; i++)
#pragma unroll
                for (int j = 0; j < 10; j++) acc[i][j] += a[i]*w[j];
        }
        __syncthreads();
    }
#pragma unroll
    for (int i = 0; i < 8; i++) {
        int row = m0 + ty*8 + i;
#pragma unroll
        for (int j = 0; j < 10; j++) {
            int n = tx*10 + j;
            if (n < NWOUT)
                g_Rb[(size_t)row*RP + n] = __float2bfloat16(acc[i][j]);
            else if (n < 80)
                g_Rb[(size_t)row*RP + n] = __float2bfloat16(0.0f);
            else {
                int nn = n - 80;
                if (nn < NWOUT) g_F[(size_t)row*FP + nn] = acc[i][j];
            }
        }
        // zero-pad R cols [80,128)
        for (int c = 80 + tx; c < RP; c += 16)
            g_Rb[(size_t)row*RP + c] = __float2bfloat16(0.0f);
    }
}

// ============== GEMM1 (e4m3 mma k32 + ldmatrix, cp.async double-buffered) ====
__global__ __launch_bounds__(256) void k_gemm1_f8(const float* __restrict__ bias) {
    __shared__ __align__(16) unsigned char As[2][128*AP8];
    __shared__ __align__(16) unsigned char Bs[2][128*AP8];
    const int bm = blockIdx.y*128, bn = blockIdx.x*128;
    const int tid = threadIdx.x, lane = tid & 31, wid = tid >> 5;
    const int wm = (wid >> 2)*64, wn = (wid & 3)*32;
    const int g = lane >> 2, t4 = lane & 3;
    float acc[4][4][4];
#pragma unroll
    for (int i = 0; i < 4; i++)
#pragma unroll
        for (int j = 0; j < 4; j++)
#pragma unroll
            for (int r = 0; r < 4; r++) acc[i][j][r] = 0.0f;

    const int a_off = (wm + (lane & 7) + 8*((lane >> 3) & 1))*AP8 + 16*(lane >> 4);
    const int b_off = (wn + (lane & 7) + 8*((lane >> 3) & 1))*AP8 + 16*(lane >> 4);
    const uint32_t AsB[2] = { svta(&As[0][0]), svta(&As[1][0]) };
    const uint32_t BsB[2] = { svta(&Bs[0][0]), svta(&Bs[1][0]) };

    auto stage = [&](int buf, int k0) {
#pragma unroll
        for (int q = 0; q < 2; q++) {
            int idx = tid + q*256;
            int r = idx >> 2, c16 = (idx & 3) << 4;
            cpa16(svta(&As[buf][r*AP8 + c16]),
                  g_feat8 + (size_t)(bm + r)*DIM + k0 + c16);
            int n = bn + r;
            int ok = (n < PM1);
            cpa16p(svta(&Bs[buf][r*AP8 + c16]),
                   g_attw8 + (size_t)(ok ? n : 0)*DIM + k0 + c16, ok);
        }
    };

    stage(0, 0);
    asm volatile("cp.async.commit_group;");
    int buf = 0;
    const int NK = DIM/64;   // 11
    for (int it = 0; it < NK; it++) {
        if (it + 1 < NK) {
            stage(buf ^ 1, (it + 1)*64);
            asm volatile("cp.async.commit_group;");
            asm volatile("cp.async.wait_group 1;");
        } else {
            asm volatile("cp.async.wait_group 0;");
        }
        __syncthreads();
#pragma unroll
        for (int ks = 0; ks < 2; ks++) {
            uint32_t af[4][4], bq[2][4];
#pragma unroll
            for (int mt = 0; mt < 4; mt++)
                ldsm4(af[mt], AsB[buf] + a_off + mt*16*AP8 + ks*32);
#pragma unroll
            for (int ntp = 0; ntp < 2; ntp++)
                ldsm4(bq[ntp], BsB[buf] + b_off + ntp*16*AP8 + ks*32);
#pragma unroll
            for (int mt = 0; mt < 4; mt++)
#pragma unroll
                for (int nt = 0; nt < 4; nt++) {
                    int ntp = nt >> 1, sub = nt & 1;
                    mma_f8(acc[mt][nt], af[mt], bq[ntp][sub], bq[ntp][sub + 2]);
                }
        }
        __syncthreads();
        buf ^= 1;
    }
#pragma unroll
    for (int mt = 0; mt < 4; mt++) {
        int r0 = bm + wm + mt*16 + g;
#pragma unroll
        for (int nt = 0; nt < 4; nt++) {
            int n0 = bn + wn + nt*8 + t4*2;
            if (n0 < PM1)
                g_attb16[(size_t)r0*PM1 + n0]       = __float2bfloat16(acc[mt][nt][0]*SCORE_INV + bias[n0]);
            if (n0+1 < PM1)
                g_attb16[(size_t)r0*PM1 + n0+1]     = __float2bfloat16(acc[mt][nt][1]*SCORE_INV + bias[n0+1]);
            if (n0 < PM1)
                g_attb16[(size_t)(r0+8)*PM1 + n0]   = __float2bfloat16(acc[mt][nt][2]*SCORE_INV + bias[n0]);
            if (n0+1 < PM1)
                g_attb16[(size_t)(r0+8)*PM1 + n0+1] = __float2bfloat16(acc[mt][nt][3]*SCORE_INV + bias[n0+1]);
        }
    }
}

// ---------------- softmax: bf16 in, bf16 SHIFTED dense row out ---------------
#define SITER ((PM1 + 255)/256)   // 11
__global__ __launch_bounds__(256) void k_softmax() {
    __shared__ float red[256];
    const size_t base  = (size_t)blockIdx.x * PM1;
    const size_t obase = (size_t)blockIdx.x * P;
    const int m = blockIdx.x % P;
    const int t = threadIdx.x;
    float vals[SITER];
    float mx = -1e30f;
#pragma unroll
    for (int j = 0; j < SITER; j++) {
        int i = t + j*256;
        float v = (i < PM1) ? __bfloat162float(g_attb16[base + i]) : -1e30f;
        vals[j] = v; mx = fmaxf(mx, v);
    }
    red[t] = mx; __syncthreads();
    for (int s = 128; s > 0; s >>= 1) { if (t < s) red[t] = fmaxf(red[t], red[t+s]); __syncthreads(); }
    mx = red[0]; __syncthreads();
    float sum = 0.0f;
#pragma unroll
    for (int j = 0; j < SITER; j++) {
        int i = t + j*256;
        float e = (i < PM1) ? __expf(vals[j] - mx) : 0.0f;
        vals[j] = e; sum += e;
    }
    red[t] = sum; __syncthreads();
    for (int s = 128; s > 0; s >>= 1) { if (t < s) red[t] += red[t+s]; __syncthreads(); }
    float inv = 1.0f / red[0];
#pragma unroll
    for (int j = 0; j < SITER; j++) {
        int i = t + j*256;
        if (i < PM1)
            g_attsh[obase + i + (i >= m)] = __float2bfloat16(vals[j] * inv);
    }
    if (t == 0) g_attsh[obase + m] = __float2bfloat16(0.0f);
}

// ============== GEMM3 (bf16 mma): out = A_shift @ R + F + bias + anchors =====
// per batch: M=2784 (guard), N=128 (75 valid, rest zero), K=2784.
__global__ __launch_bounds__(256) void k_gemm3_bf(const float* __restrict__ cls_b,
                                                  const float* __restrict__ reg_b,
                                                  const float* __restrict__ anchors,
                                                  float* __restrict__ out) {
    __shared__ __align__(16) __nv_bfloat16 As[2][128*AKH];
    __shared__ __align__(16) __nv_bfloat16 Bs[2][32*BNH];
    const int b  = blockIdx.z;
    const int m0 = blockIdx.y*128;
    const int tid = threadIdx.x, lane = tid & 31, wid = tid >> 5;
    const int wm = (wid >> 2)*64, wn = (wid & 3)*32;
    const int g = lane >> 2, t4 = lane & 3;
    const __nv_bfloat16* attsh = g_attsh + (size_t)b*P*P;
    const __nv_bfloat16* Rb    = g_Rb    + (size_t)b*P*RP;
    float acc[4][4][4];
#pragma unroll
    for (int i = 0; i < 4; i++)
#pragma unroll
        for (int j = 0; j < 4; j++)
#pragma unroll
            for (int r = 0; r < 4; r++) acc[i][j][r] = 0.0f;

    const int a_off  = (wm + (lane & 7) + 8*((lane >> 3) & 1))*AKH + 8*(lane >> 4);
    const int bt_off = ((lane & 7) + 8*((lane >> 3) & 1))*BNH + wn + 8*(lane >> 4);
    const uint32_t AsB[2] = { svta(&As[0][0]), svta(&As[1][0]) };
    const uint32_t BsB[2] = { svta(&Bs[0][0]), svta(&Bs[1][0]) };

    auto stage = [&](int buf, int k0) {
#pragma unroll
        for (int q = 0; q < 2; q++) {
            int idx = tid + q*256;
            int r = idx >> 2, c8 = (idx & 3) << 3;
            int gm = m0 + r;
            int ok = (gm < P);
            cpa16p(svta(&As[buf][r*AKH + c8]),
                   attsh + (size_t)(ok ? gm : 0)*P + k0 + c8, ok);
        }
#pragma unroll
        for (int q = 0; q < 2; q++) {
            int idx = tid + q*256;
            int kr = idx >> 4, c8 = (idx & 15) << 3;
            cpa16(svta(&Bs[buf][kr*BNH + c8]),
                  Rb + (size_t)(k0 + kr)*RP + c8);
        }
    };

    stage(0, 0);
    asm volatile("cp.async.commit_group;");
    int buf = 0;
    const int NK = P/32;   // 87
    for (int it = 0; it < NK; it++) {
        if (it + 1 < NK) {
            stage(buf ^ 1, (it + 1)*32);
            asm volatile("cp.async.commit_group;");
            asm volatile("cp.async.wait_group 1;");
        } else {
            asm volatile("cp.async.wait_group 0;");
        }
        __syncthreads();
#pragma unroll
        for (int ks = 0; ks < 2; ks++) {
            const int kk = ks*16;
            uint32_t af[4][4], bq[2][4];
#pragma unroll
            for (int mt = 0; mt < 4; mt++)
                ldsm4(af[mt], AsB[buf] + 2*(a_off + mt*16*AKH + kk));
#pragma unroll
            for (int ntp = 0; ntp < 2; ntp++)
                ldsm4t(bq[ntp], BsB[buf] + 2*(bt_off + kk*BNH + ntp*16));
#pragma unroll
            for (int mt = 0; mt < 4; mt++)
#pragma unroll
                for (int nt = 0; nt < 4; nt++)
                    mma_bf16(acc[mt][nt], af[mt], &bq[nt >> 1][(nt & 1)*2]);
        }
        __syncthreads();
        buf ^= 1;
    }

    // fused final epilogue: add F + bias, then anchors/output assembly
    const size_t O0 = 0;
    const size_t O1 = (size_t)M_TOT * 72;
    const size_t O2 = O1 + M_TOT;
    const size_t O3 = O2 + M_TOT;
#pragma unroll
    for (int mt = 0; mt < 4; mt++) {
        int r0 = m0 + wm + mt*16 + g;
#pragma unroll
        for (int nt = 0; nt < 4; nt++) {
            int n0c = wn + nt*8 + t4*2;
#pragma unroll
            for (int rr = 0; rr < 2; rr++) {
                int pl = r0 + 8*rr;
                if (pl >= P) continue;
                int row = b*P + pl;
#pragma unroll
                for (int e = 0; e < 2; e++) {
                    int n = n0c + e;
                    if (n >= NWOUT) continue;
                    float val = acc[mt][nt][rr*2 + e]
                              + g_F[(size_t)row*FP + n]
                              + (n < 2 ? cls_b[n] : reg_b[n-2]);
                    if (n < 2) {
                        out[O3 + (size_t)row*2 + n] = val;
                    } else if (n == 2) {
                        out[O2 + row] = anchors[pl*74 + 1] + val;
                        out[O1 + row] = anchors[pl*74 + 0];
                    } else {
                        out[O0 + (size_t)row*72 + (n-3)] = anchors[pl*74 + 2 + (n-3)] + val;
                    }
                }
            }
        }
    }
}

// ---------------- launch ----------------
extern "C" void kernel_launch(void* const* d_in, const int* in_sizes, int n_in,
                              void* d_out, int out_size) {
    const float* x       = (const float*)d_in[0];
    const float* conv_w  = (const float*)d_in[1];
    const float* conv_b  = (const float*)d_in[2];
    const float* att_w   = (const float*)d_in[3];
    const float* att_b   = (const float*)d_in[4];
    const float* cls_w   = (const float*)d_in[5];
    const float* cls_b   = (const float*)d_in[6];
    const float* reg_w   = (const float*)d_in[7];
    const float* reg_b   = (const float*)d_in[8];
    const float* anchors = (const float*)d_in[9];
    const int*   cut_x   = (const int*)d_in[10];
    const unsigned char* invalid = (const unsigned char*)d_in[11];
    float* out = (float*)d_out;
    (void)in_sizes; (void)n_in; (void)out_size;

    k_detect_inv<<<1, 1024>>>(invalid);
    k_conv<<<dim3(HW, BATCH), 64>>>(x, conv_w, conv_b);
    k_cvt_attw<<<(PM1*DIM + 255)/256, 256>>>(att_w);
    k_gather<<<M_TOT, 128>>>(cut_x);
    k_head<<<M_TOT/128, 256>>>(cls_w, reg_w);
    k_gemm1_f8<<<dim3((PM1 + 127)/128, M_TOT/128), 256>>>(att_b);
    k_softmax<<<M_TOT, 256>>>();
    k_gemm3_bf<<<dim3(1, (P + 127)/128, BATCH), 256>>>(cls_b, reg_b, anchors, out);
}